// round 4
// baseline (speedup 1.0000x reference)
#include <cuda_runtime.h>
#include <math.h>
#include <stdint.h>

// Problem constants: B=32, C=128, H=W=64, WS=8, SHIFT=4, HEADS=4, TOK=64, NW=64, DH=32, HID=512
#define N_WIN   2048
#define N_TOK   131072

// ---------------- scratch ----------------
__device__ float g_skip[N_TOK * 128];        // [tokg][c], tokg = b*4096 + y*64 + x (orig coords)
__device__ float g_bias[4 * 64 * 64];        // [h][q][k]

// ---------------- tf32 mma helpers ----------------
__device__ __forceinline__ uint32_t f2tf32(float x) {
    uint32_t r;
    asm("cvt.rna.tf32.f32 %0, %1;" : "=r"(r) : "f"(x));
    return r;
}

__device__ __forceinline__ void mma8(float c[4], uint32_t a0, uint32_t a1, uint32_t a2, uint32_t a3,
                                     uint32_t b0, uint32_t b1) {
    asm volatile("mma.sync.aligned.m16n8k8.row.col.f32.tf32.tf32.f32 "
                 "{%0,%1,%2,%3},{%4,%5,%6,%7},{%8,%9},{%0,%1,%2,%3};"
                 : "+f"(c[0]), "+f"(c[1]), "+f"(c[2]), "+f"(c[3])
                 : "r"(a0), "r"(a1), "r"(a2), "r"(a3), "r"(b0), "r"(b1));
}

// One 32-K-chunk of the 64x128 block GEMM. A resident in smem with row stride ASTR.
// Bs holds the current 32x128 weight chunk at [k][136].
template<int ASTR>
__device__ __forceinline__ void mma_chunk(const uint32_t* __restrict__ As, const uint32_t* __restrict__ Bs,
                                          int m0w, int n0w, int g, int tg, int kbase, float acc[8][4]) {
#pragma unroll
    for (int ks = 0; ks < 4; ks++) {
        int kk = kbase + ks * 8;
        int bk = ks * 8;
        uint32_t a0 = As[(m0w + g) * ASTR + kk + tg];
        uint32_t a1 = As[(m0w + g + 8) * ASTR + kk + tg];
        uint32_t a2 = As[(m0w + g) * ASTR + kk + tg + 4];
        uint32_t a3 = As[(m0w + g + 8) * ASTR + kk + tg + 4];
#pragma unroll
        for (int s = 0; s < 8; s++) {
            uint32_t b0 = Bs[(bk + tg) * 136 + n0w + s * 8 + g];
            uint32_t b1 = Bs[(bk + tg + 4) * 136 + n0w + s * 8 + g];
            mma8(acc[s], a0, a1, a2, a3, b0, b1);
        }
    }
}

// load 32x128 weight chunk (row stride WSTR) into Bs[32][136] as tf32 (256 threads)
__device__ __forceinline__ void load_bs(uint32_t* __restrict__ Bs, const float* __restrict__ W,
                                        int row0, int WSTR, int ncol0, int t) {
#pragma unroll
    for (int it = 0; it < 4; it++) {
        int p = it * 256 + t;
        int k = p >> 5, n4 = p & 31;
        float4 v = *(const float4*)&W[(size_t)(row0 + k) * WSTR + ncol0 + n4 * 4];
        uint4 u = make_uint4(f2tf32(v.x), f2tf32(v.y), f2tf32(v.z), f2tf32(v.w));
        *(uint4*)&Bs[k * 136 + n4 * 4] = u;
    }
}

#define SMEM_A 181760
#define SMEM_B 183296

// ---------------- 0. meta-MLP relative position bias ----------------
__global__ void bias_kernel(const float* __restrict__ w1, const float* __restrict__ b1,
                            const float* __restrict__ w2, const float* __restrict__ b2) {
    int p = blockIdx.x * 256 + threadIdx.x;
    int q = p >> 6, k = p & 63;
    float dy = (float)((q >> 3) - (k >> 3));
    float dx = (float)((q & 7) - (k & 7));
    float r0 = copysignf(log1pf(fabsf(dy)), dy);
    float r1 = copysignf(log1pf(fabsf(dx)), dx);
    float a0 = 0.f, a1 = 0.f, a2 = 0.f, a3 = 0.f;
    for (int j = 0; j < 256; j++) {
        float h = r0 * w1[j] + r1 * w1[256 + j] + b1[j];
        h = fmaxf(h, 0.f);
        a0 += h * w2[j * 4 + 0];
        a1 += h * w2[j * 4 + 1];
        a2 += h * w2[j * 4 + 2];
        a3 += h * w2[j * 4 + 3];
    }
    g_bias[0 * 4096 + p] = a0 + b2[0];
    g_bias[1 * 4096 + p] = a1 + b2[1];
    g_bias[2 * 4096 + p] = a2 + b2[2];
    g_bias[3 * 4096 + p] = a3 + b2[3];
}

// ---------------- 1. winblock: gather + QKV + attention + proj + LN1 + residual ----------------
__global__ void __launch_bounds__(256) winblock_kernel(
        const float* __restrict__ x,
        const float* __restrict__ qkv_w, const float* __restrict__ qkv_b,
        const float* __restrict__ proj_w, const float* __restrict__ proj_b,
        const float* __restrict__ tau,
        const float* __restrict__ lg, const float* __restrict__ lb) {
    extern __shared__ __align__(16) unsigned char sm[];
    uint32_t* Xs   = (uint32_t*)sm;                  // [64][132]  (later Ao, later Cs fp32)
    uint32_t* Bs   = (uint32_t*)(sm + 33792);        // [32][136]  (also Pscr: 8 warps x 16 x 68)
    uint32_t* Qs   = (uint32_t*)(sm + 68608);        // [4][64][36]
    uint32_t* Ks   = (uint32_t*)(sm + 105472);
    uint32_t* Vs   = (uint32_t*)(sm + 142336);
    float*    qn   = (float*)(sm + 179200);          // [4][64]
    float*    kn   = (float*)(sm + 180224);          // [4][64]
    int*      cnti = (int*)(sm + 181248);            // [64]
    float*    stau = (float*)(sm + 181504);          // [4]

    int t = threadIdx.x;
    int win = blockIdx.x;
    int b = win >> 6, wy = (win >> 3) & 7, wx = win & 7;

    const int lane = t & 31, g = lane >> 2, tg = lane & 3;
    const int warp = t >> 5;
    const int wm = warp & 3, wn = warp >> 2;
    const int m0w = wm * 16, n0w = wn * 64;

    // ---- phase 0: gather x (roll -SHIFT) -> Xs tf32 [tok][132]; mask/tau ----
#pragma unroll
    for (int it = 0; it < 8; it++) {
        int p = it * 256 + t;
        int c = p >> 4;
        int r = (p >> 1) & 7;
        int half = p & 1;
        int y  = (wy * 8 + r + 4) & 63;
        int xb = (wx * 8 + 4 + half * 4) & 63;
        float4 v = *(const float4*)&x[((size_t)(b * 128 + c) * 64 + y) * 64 + xb];
        int tok = r * 8 + half * 4;
        Xs[(tok + 0) * 132 + c] = f2tf32(v.x);
        Xs[(tok + 1) * 132 + c] = f2tf32(v.y);
        Xs[(tok + 2) * 132 + c] = f2tf32(v.z);
        Xs[(tok + 3) * 132 + c] = f2tf32(v.w);
    }
    if (t < 64) {
        int ys = wy * 8 + (t >> 3);
        int xs = wx * 8 + (t & 7);
        int ry = ys < 56 ? 0 : (ys < 60 ? 1 : 2);
        int rx = xs < 56 ? 0 : (xs < 60 ? 1 : 2);
        cnti[t] = ry * 3 + rx;
    }
    if (t < 4) stau[t] = fmaxf(tau[t], 0.01f);

    // ---- phase 1: QKV GEMM (A resident) ----
    for (int nb = 0; nb < 3; nb++) {
        float acc[8][4] = {};
        for (int k0 = 0; k0 < 4; k0++) {
            __syncthreads();
            load_bs(Bs, qkv_w, k0 * 32, 384, nb * 128, t);
            __syncthreads();
            mma_chunk<132>(Xs, Bs, m0w, n0w, g, tg, k0 * 32, acc);
        }
        // epilogue: bias, norms (q/k), store tf32 to Qs/Ks/Vs
        int r0 = m0w + g, r1 = r0 + 8;
        int h0 = n0w >> 5;                 // first head in this warp's 64 cols
        float nsq[2][2] = {};
        uint32_t* dst = (nb == 0) ? Qs : (nb == 1) ? Ks : Vs;
#pragma unroll
        for (int s = 0; s < 8; s++) {
            int nl = n0w + s * 8 + 2 * tg;
            float b0v = qkv_b[nb * 128 + nl], b1v = qkv_b[nb * 128 + nl + 1];
            float v0 = acc[s][0] + b0v, v1 = acc[s][1] + b1v;
            float v2 = acc[s][2] + b0v, v3 = acc[s][3] + b1v;
            int hloc = s >> 2;
            nsq[0][hloc] += v0 * v0 + v1 * v1;
            nsq[1][hloc] += v2 * v2 + v3 * v3;
            int h = h0 + hloc;
            int dloc = (s & 3) * 8 + 2 * tg;
            dst[h * 2304 + r0 * 36 + dloc]     = f2tf32(v0);
            dst[h * 2304 + r0 * 36 + dloc + 1] = f2tf32(v1);
            dst[h * 2304 + r1 * 36 + dloc]     = f2tf32(v2);
            dst[h * 2304 + r1 * 36 + dloc + 1] = f2tf32(v3);
        }
        if (nb < 2) {
#pragma unroll
            for (int o = 1; o <= 2; o <<= 1) {
                nsq[0][0] += __shfl_xor_sync(0xffffffffu, nsq[0][0], o);
                nsq[0][1] += __shfl_xor_sync(0xffffffffu, nsq[0][1], o);
                nsq[1][0] += __shfl_xor_sync(0xffffffffu, nsq[1][0], o);
                nsq[1][1] += __shfl_xor_sync(0xffffffffu, nsq[1][1], o);
            }
            if (tg == 0) {
                float* np = (nb == 0) ? qn : kn;
                np[h0 * 64 + r0]       = sqrtf(nsq[0][0]);
                np[h0 * 64 + r1]       = sqrtf(nsq[1][0]);
                np[(h0 + 1) * 64 + r0] = sqrtf(nsq[0][1]);
                np[(h0 + 1) * 64 + r1] = sqrtf(nsq[1][1]);
            }
        }
    }
    __syncthreads();   // QKV/qn/kn complete; Xs dead -> reuse as Ao

    // ---- phase 2: attention. warp w: head = w>>1, rows (w&1)*32 .. +31 ----
    {
        int hd = warp >> 1;
        int mb = (warp & 1) * 32;
        const uint32_t* Qh = Qs + hd * 2304;
        const uint32_t* Kh = Ks + hd * 2304;
        const uint32_t* Vh = Vs + hd * 2304;
        uint32_t* Ao = Xs;                           // [64][132] tf32 output (proj A)
        uint32_t* Pw = Bs + warp * (16 * 68);        // per-warp P scratch
        float tv = stau[hd];

        for (int mt = 0; mt < 2; mt++) {
            int m0 = mb + mt * 16;
            int r0 = m0 + g, r1 = r0 + 8;

            float acc[8][4] = {};
#pragma unroll
            for (int ks = 0; ks < 4; ks++) {
                int kk = ks * 8;
                uint32_t a0 = Qh[r0 * 36 + kk + tg];
                uint32_t a1 = Qh[r1 * 36 + kk + tg];
                uint32_t a2 = Qh[r0 * 36 + kk + tg + 4];
                uint32_t a3 = Qh[r1 * 36 + kk + tg + 4];
#pragma unroll
                for (int s = 0; s < 8; s++) {
                    uint32_t b0 = Kh[(s * 8 + g) * 36 + kk + tg];
                    uint32_t b1 = Kh[(s * 8 + g) * 36 + kk + tg + 4];
                    mma8(acc[s], a0, a1, a2, a3, b0, b1);
                }
            }

            float qn0 = qn[hd * 64 + r0], qn1 = qn[hd * 64 + r1];
            int mq0 = cnti[r0], mq1 = cnti[r1];
            const float* bias0 = &g_bias[hd * 4096 + r0 * 64];
            const float* bias1 = &g_bias[hd * 4096 + r1 * 64];
#pragma unroll
            for (int s = 0; s < 8; s++) {
                int c0 = s * 8 + 2 * tg;
                float kn0 = kn[hd * 64 + c0], kn1 = kn[hd * 64 + c0 + 1];
                float2 bA = *(const float2*)&bias0[c0];
                float2 bB = *(const float2*)&bias1[c0];
                int mk0 = cnti[c0], mk1 = cnti[c0 + 1];
                acc[s][0] = acc[s][0] / fmaxf(qn0 * kn0, 1e-6f) / tv + bA.x + (mq0 != mk0 ? -100.f : 0.f);
                acc[s][1] = acc[s][1] / fmaxf(qn0 * kn1, 1e-6f) / tv + bA.y + (mq0 != mk1 ? -100.f : 0.f);
                acc[s][2] = acc[s][2] / fmaxf(qn1 * kn0, 1e-6f) / tv + bB.x + (mq1 != mk0 ? -100.f : 0.f);
                acc[s][3] = acc[s][3] / fmaxf(qn1 * kn1, 1e-6f) / tv + bB.y + (mq1 != mk1 ? -100.f : 0.f);
            }

            float mx0 = -1e30f, mx1 = -1e30f;
#pragma unroll
            for (int s = 0; s < 8; s++) {
                mx0 = fmaxf(mx0, fmaxf(acc[s][0], acc[s][1]));
                mx1 = fmaxf(mx1, fmaxf(acc[s][2], acc[s][3]));
            }
#pragma unroll
            for (int o = 1; o <= 2; o <<= 1) {
                mx0 = fmaxf(mx0, __shfl_xor_sync(0xffffffffu, mx0, o));
                mx1 = fmaxf(mx1, __shfl_xor_sync(0xffffffffu, mx1, o));
            }
            float sm0 = 0.f, sm1 = 0.f;
#pragma unroll
            for (int s = 0; s < 8; s++) {
                acc[s][0] = expf(acc[s][0] - mx0);
                acc[s][1] = expf(acc[s][1] - mx0);
                acc[s][2] = expf(acc[s][2] - mx1);
                acc[s][3] = expf(acc[s][3] - mx1);
                sm0 += acc[s][0] + acc[s][1];
                sm1 += acc[s][2] + acc[s][3];
            }
#pragma unroll
            for (int o = 1; o <= 2; o <<= 1) {
                sm0 += __shfl_xor_sync(0xffffffffu, sm0, o);
                sm1 += __shfl_xor_sync(0xffffffffu, sm1, o);
            }
            float inv0 = 1.f / sm0, inv1 = 1.f / sm1;
#pragma unroll
            for (int s = 0; s < 8; s++) {
                int c0 = s * 8 + 2 * tg;
                Pw[g * 68 + c0]           = f2tf32(acc[s][0] * inv0);
                Pw[g * 68 + c0 + 1]       = f2tf32(acc[s][1] * inv0);
                Pw[(g + 8) * 68 + c0]     = f2tf32(acc[s][2] * inv1);
                Pw[(g + 8) * 68 + c0 + 1] = f2tf32(acc[s][3] * inv1);
            }
            __syncwarp();

            float oacc[4][4] = {};
#pragma unroll
            for (int ks = 0; ks < 8; ks++) {
                int kk = ks * 8;
                uint32_t a0 = Pw[g * 68 + kk + tg];
                uint32_t a1 = Pw[(g + 8) * 68 + kk + tg];
                uint32_t a2 = Pw[g * 68 + kk + tg + 4];
                uint32_t a3 = Pw[(g + 8) * 68 + kk + tg + 4];
#pragma unroll
                for (int s2 = 0; s2 < 4; s2++) {
                    uint32_t b0 = Vh[(kk + tg) * 36 + s2 * 8 + g];
                    uint32_t b1 = Vh[(kk + tg + 4) * 36 + s2 * 8 + g];
                    mma8(oacc[s2], a0, a1, a2, a3, b0, b1);
                }
            }
            __syncwarp();   // P reads done before next mt overwrites Pw
#pragma unroll
            for (int s2 = 0; s2 < 4; s2++) {
                int dc = hd * 32 + s2 * 8 + 2 * tg;
                Ao[r0 * 132 + dc]     = f2tf32(oacc[s2][0]);
                Ao[r0 * 132 + dc + 1] = f2tf32(oacc[s2][1]);
                Ao[r1 * 132 + dc]     = f2tf32(oacc[s2][2]);
                Ao[r1 * 132 + dc + 1] = f2tf32(oacc[s2][3]);
            }
        }
    }

    // ---- phase 3: proj GEMM + LN1 + residual ----
    {
        float acc[8][4] = {};
        for (int k0 = 0; k0 < 4; k0++) {
            __syncthreads();            // first iter: Ao complete / Pscr dead
            load_bs(Bs, proj_w, k0 * 32, 128, 0, t);
            __syncthreads();
            mma_chunk<132>(Xs, Bs, m0w, n0w, g, tg, k0 * 32, acc);
        }
        __syncthreads();
        float* Cs = (float*)Xs;          // overwrite Ao (dead after GEMM)
#pragma unroll
        for (int s = 0; s < 8; s++) {
            int c = n0w + s * 8 + 2 * tg;
            float b0v = proj_b[c], b1v = proj_b[c + 1];
            Cs[(m0w + g) * 132 + c]         = acc[s][0] + b0v;
            Cs[(m0w + g) * 132 + c + 1]     = acc[s][1] + b1v;
            Cs[(m0w + g + 8) * 132 + c]     = acc[s][2] + b0v;
            Cs[(m0w + g + 8) * 132 + c + 1] = acc[s][3] + b1v;
        }
        __syncthreads();

        float4 lg4 = *(const float4*)&lg[lane * 4];
        float4 lb4 = *(const float4*)&lb[lane * 4];
        for (int i = 0; i < 8; i++) {
            int tk = warp * 8 + i;
            float4 v = *(const float4*)&Cs[tk * 132 + lane * 4];
            float s  = v.x + v.y + v.z + v.w;
            float ss = v.x * v.x + v.y * v.y + v.z * v.z + v.w * v.w;
#pragma unroll
            for (int o = 16; o; o >>= 1) {
                s  += __shfl_xor_sync(0xffffffffu, s, o);
                ss += __shfl_xor_sync(0xffffffffu, ss, o);
            }
            float mu = s * (1.f / 128.f);
            float var = ss * (1.f / 128.f) - mu * mu;
            float rs = rsqrtf(var + 1e-5f);

            int y  = (wy * 8 + (tk >> 3) + 4) & 63;
            int xx = (wx * 8 + (tk & 7) + 4) & 63;
            const float* xr = x + ((size_t)(b * 128 + lane * 4) * 64 + y) * 64 + xx;
            float4 o4;
            o4.x = (v.x - mu) * rs * lg4.x + lb4.x + xr[0];
            o4.y = (v.y - mu) * rs * lg4.y + lb4.y + xr[4096];
            o4.z = (v.z - mu) * rs * lg4.z + lb4.z + xr[8192];
            o4.w = (v.w - mu) * rs * lg4.w + lb4.w + xr[12288];
            *(float4*)&g_skip[((size_t)b * 4096 + y * 64 + xx) * 128 + lane * 4] = o4;
        }
    }
}

// ---------------- 2. ffnblock: FFN1 + GELU + FFN2 + LN2 + residual + transposed out ----------------
__global__ void __launch_bounds__(256) ffnblock_kernel(
        const float* __restrict__ w1, const float* __restrict__ b1,
        const float* __restrict__ w2, const float* __restrict__ b2,
        const float* __restrict__ lg, const float* __restrict__ lb,
        float* __restrict__ out) {
    extern __shared__ __align__(16) unsigned char sm[];
    uint32_t* Xs = (uint32_t*)sm;             // [64][132] skip tf32 (later Cs fp32)
    uint32_t* Bs = (uint32_t*)(sm + 33792);   // [32][136]
    uint32_t* Hs = (uint32_t*)(sm + 51200);   // [64][516] h1 tf32

    int t = threadIdx.x;
    int tile = blockIdx.x;                    // 64 consecutive tokens
    const int lane = t & 31, g = lane >> 2, tg = lane & 3;
    const int warp = t >> 5;
    const int wm = warp & 3, wn = warp >> 2;
    const int m0w = wm * 16, n0w = wn * 64;

    const float* sp = g_skip + (size_t)tile * 64 * 128;
#pragma unroll
    for (int it = 0; it < 8; it++) {
        int p = it * 256 + t;
        int tok = p >> 5, c4 = p & 31;
        float4 v = *(const float4*)&sp[tok * 128 + c4 * 4];
        Xs[tok * 132 + c4 * 4 + 0] = f2tf32(v.x);
        Xs[tok * 132 + c4 * 4 + 1] = f2tf32(v.y);
        Xs[tok * 132 + c4 * 4 + 2] = f2tf32(v.z);
        Xs[tok * 132 + c4 * 4 + 3] = f2tf32(v.w);
    }

    // ---- FFN1 + GELU -> Hs ----
    for (int nb = 0; nb < 4; nb++) {
        float acc[8][4] = {};
        for (int k0 = 0; k0 < 4; k0++) {
            __syncthreads();
            load_bs(Bs, w1, k0 * 32, 512, nb * 128, t);
            __syncthreads();
            mma_chunk<132>(Xs, Bs, m0w, n0w, g, tg, k0 * 32, acc);
        }
        int r0 = m0w + g, r1 = r0 + 8;
#pragma unroll
        for (int s = 0; s < 8; s++) {
            int nl = n0w + s * 8 + 2 * tg;
            int ng = nb * 128 + nl;
            float b0v = b1[ng], b1v = b1[ng + 1];
            float h0 = acc[s][0] + b0v, h1 = acc[s][1] + b1v;
            float h2 = acc[s][2] + b0v, h3 = acc[s][3] + b1v;
            h0 = 0.5f * h0 * (1.f + erff(h0 * 0.70710678118654752f));
            h1 = 0.5f * h1 * (1.f + erff(h1 * 0.70710678118654752f));
            h2 = 0.5f * h2 * (1.f + erff(h2 * 0.70710678118654752f));
            h3 = 0.5f * h3 * (1.f + erff(h3 * 0.70710678118654752f));
            Hs[r0 * 516 + ng]     = f2tf32(h0);
            Hs[r0 * 516 + ng + 1] = f2tf32(h1);
            Hs[r1 * 516 + ng]     = f2tf32(h2);
            Hs[r1 * 516 + ng + 1] = f2tf32(h3);
        }
    }

    // ---- FFN2 (K=512) ----
    float acc2[8][4] = {};
    for (int k0 = 0; k0 < 16; k0++) {
        __syncthreads();                 // first iter also guards Hs writes
        load_bs(Bs, w2, k0 * 32, 128, 0, t);
        __syncthreads();
        mma_chunk<516>(Hs, Bs, m0w, n0w, g, tg, k0 * 32, acc2);
    }
    __syncthreads();
    float* Cs = (float*)Xs;              // Xs dead after ffn1
#pragma unroll
    for (int s = 0; s < 8; s++) {
        int c = n0w + s * 8 + 2 * tg;
        float b0v = b2[c], b1v = b2[c + 1];
        Cs[(m0w + g) * 132 + c]         = acc2[s][0] + b0v;
        Cs[(m0w + g) * 132 + c + 1]     = acc2[s][1] + b1v;
        Cs[(m0w + g + 8) * 132 + c]     = acc2[s][2] + b0v;
        Cs[(m0w + g + 8) * 132 + c + 1] = acc2[s][3] + b1v;
    }
    __syncthreads();

    // LN2 + residual (fp32 skip from global, L2-hot)
    float4 lg4 = *(const float4*)&lg[lane * 4];
    float4 lb4 = *(const float4*)&lb[lane * 4];
    for (int i = 0; i < 8; i++) {
        int tk = warp * 8 + i;
        float4 v = *(const float4*)&Cs[tk * 132 + lane * 4];
        float s  = v.x + v.y + v.z + v.w;
        float ss = v.x * v.x + v.y * v.y + v.z * v.z + v.w * v.w;
#pragma unroll
        for (int o = 16; o; o >>= 1) {
            s  += __shfl_xor_sync(0xffffffffu, s, o);
            ss += __shfl_xor_sync(0xffffffffu, ss, o);
        }
        float mu = s * (1.f / 128.f);
        float var = ss * (1.f / 128.f) - mu * mu;
        float rs = rsqrtf(var + 1e-5f);
        float4 sk = *(const float4*)&sp[tk * 128 + lane * 4];
        float4 o4;
        o4.x = (v.x - mu) * rs * lg4.x + lb4.x + sk.x;
        o4.y = (v.y - mu) * rs * lg4.y + lb4.y + sk.y;
        o4.z = (v.z - mu) * rs * lg4.z + lb4.z + sk.z;
        o4.w = (v.w - mu) * rs * lg4.w + lb4.w + sk.w;
        *(float4*)&Cs[tk * 132 + lane * 4] = o4;
    }
    __syncthreads();

    // transposed write: tile = b*64 + y, token-local = x
    int b = tile >> 6, y = tile & 63;
    for (int it = 0; it < 32; it++) {
        int idx = it * 256 + t;
        int c = idx >> 6, xcol = idx & 63;
        out[((size_t)(b * 128 + c) * 64 + y) * 64 + xcol] = Cs[xcol * 132 + c];
    }
}

// ---------------- launch ----------------
extern "C" void kernel_launch(void* const* d_in, const int* in_sizes, int n_in,
                              void* d_out, int out_size) {
    (void)in_sizes; (void)n_in; (void)out_size;
    const float* x      = (const float*)d_in[0];
    const float* qkv_w  = (const float*)d_in[1];
    const float* qkv_b  = (const float*)d_in[2];
    const float* proj_w = (const float*)d_in[3];
    const float* proj_b = (const float*)d_in[4];
    const float* mw1    = (const float*)d_in[5];
    const float* mb1    = (const float*)d_in[6];
    const float* mw2    = (const float*)d_in[7];
    const float* mb2    = (const float*)d_in[8];
    const float* tau    = (const float*)d_in[9];
    const float* ln1_g  = (const float*)d_in[10];
    const float* ln1_b  = (const float*)d_in[11];
    const float* ln2_g  = (const float*)d_in[12];
    const float* ln2_b  = (const float*)d_in[13];
    const float* ffn_w1 = (const float*)d_in[14];
    const float* ffn_b1 = (const float*)d_in[15];
    const float* ffn_w2 = (const float*)d_in[16];
    const float* ffn_b2 = (const float*)d_in[17];
    float* out = (float*)d_out;

    cudaFuncSetAttribute(winblock_kernel, cudaFuncAttributeMaxDynamicSharedMemorySize, SMEM_A);
    cudaFuncSetAttribute(ffnblock_kernel, cudaFuncAttributeMaxDynamicSharedMemorySize, SMEM_B);

    bias_kernel<<<16, 256>>>(mw1, mb1, mw2, mb2);
    winblock_kernel<<<N_WIN, 256, SMEM_A>>>(x, qkv_w, qkv_b, proj_w, proj_b, tau, ln1_g, ln1_b);
    ffnblock_kernel<<<N_WIN, 256, SMEM_B>>>(ffn_w1, ffn_b1, ffn_w2, ffn_b2, ln2_g, ln2_b, out);
}

// round 5
// speedup vs baseline: 1.3212x; 1.3212x over previous
#include <cuda_runtime.h>
#include <math.h>
#include <stdint.h>

// Problem constants: B=32, C=128, H=W=64, WS=8, SHIFT=4, HEADS=4, TOK=64, NW=64, DH=32, HID=512
#define N_WIN   2048
#define N_TOK   131072

// ---------------- scratch ----------------
__device__ float g_q[8192 * 2048];           // [win*4+h][tok=64][d=32]
__device__ float g_k[8192 * 2048];
__device__ float g_v[8192 * 2048];
__device__ float g_attn[N_WIN * 64 * 128];   // [win][tok][c]
__device__ float g_skip[N_TOK * 128];        // [tokg][c]
__device__ float g_h1[N_TOK * 512];          // [tokg][hid]
__device__ float g_bias[4 * 64 * 64];        // [h][q][k]

// ---------------- tf32 mma helpers ----------------
__device__ __forceinline__ uint32_t f2tf32(float x) {
    uint32_t r;
    asm("cvt.rna.tf32.f32 %0, %1;" : "=r"(r) : "f"(x));
    return r;
}

__device__ __forceinline__ void mma8(float c[4], uint32_t a0, uint32_t a1, uint32_t a2, uint32_t a3,
                                     uint32_t b0, uint32_t b1) {
    asm volatile("mma.sync.aligned.m16n8k8.row.col.f32.tf32.tf32.f32 "
                 "{%0,%1,%2,%3},{%4,%5,%6,%7},{%8,%9},{%0,%1,%2,%3};"
                 : "+f"(c[0]), "+f"(c[1]), "+f"(c[2]), "+f"(c[3])
                 : "r"(a0), "r"(a1), "r"(a2), "r"(a3), "r"(b0), "r"(b1));
}

// One 32-K MMA chunk of the 64x128 block tile. A at [row][ASTR], Bs chunk at [k][136].
template<int ASTR>
__device__ __forceinline__ void mma_chunk(const uint32_t* __restrict__ As, const uint32_t* __restrict__ Bs,
                                          int m0w, int n0w, int g, int tg, int kbase, float acc[8][4]) {
#pragma unroll
    for (int ks = 0; ks < 4; ks++) {
        int kk = kbase + ks * 8;
        int bk = ks * 8;
        uint32_t a0 = As[(m0w + g) * ASTR + kk + tg];
        uint32_t a1 = As[(m0w + g + 8) * ASTR + kk + tg];
        uint32_t a2 = As[(m0w + g) * ASTR + kk + tg + 4];
        uint32_t a3 = As[(m0w + g + 8) * ASTR + kk + tg + 4];
#pragma unroll
        for (int s = 0; s < 8; s++) {
            uint32_t b0 = Bs[(bk + tg) * 136 + n0w + s * 8 + g];
            uint32_t b1 = Bs[(bk + tg + 4) * 136 + n0w + s * 8 + g];
            mma8(acc[s], a0, a1, a2, a3, b0, b1);
        }
    }
}

// prefetch a 32x128 weight chunk into registers (256 threads, 4 float4 each)
__device__ __forceinline__ void pf_b(float4 r[4], const float* __restrict__ W,
                                     int row0, int WSTR, int ncol0, int t) {
#pragma unroll
    for (int it = 0; it < 4; it++) {
        int p = it * 256 + t;
        int k = p >> 5, n4 = p & 31;
        r[it] = *(const float4*)&W[(size_t)(row0 + k) * WSTR + ncol0 + n4 * 4];
    }
}
__device__ __forceinline__ void st_b(uint32_t* __restrict__ Bs, const float4 r[4], int t) {
#pragma unroll
    for (int it = 0; it < 4; it++) {
        int p = it * 256 + t;
        int k = p >> 5, n4 = p & 31;
        *(uint4*)&Bs[k * 136 + n4 * 4] =
            make_uint4(f2tf32(r[it].x), f2tf32(r[it].y), f2tf32(r[it].z), f2tf32(r[it].w));
    }
}

#define BCH 4352                 // words per Bs chunk (32*136)
#define SMEM_ARES 68608          // Xs 33792 + 2*17408
#define SMEM_FFN2 53248          // 2*9216 (As) + 2*17408 (Bs)

// A-resident pipelined GEMM over one 128-col N-block (4 K-chunks of 32)
__device__ __forceinline__ void gemm_ares(const uint32_t* __restrict__ Xs, uint32_t* __restrict__ Bs,
                                          const float* __restrict__ W, int WSTR, int nbase,
                                          int m0w, int n0w, int g, int tg, int t, float acc[8][4]) {
    float4 pf[4];
    pf_b(pf, W, 0, WSTR, nbase, t);
#pragma unroll
    for (int k0 = 0; k0 < 4; k0++) {
        uint32_t* buf = Bs + (k0 & 1) * BCH;
        st_b(buf, pf, t);
        __syncthreads();
        if (k0 < 3) pf_b(pf, W, (k0 + 1) * 32, WSTR, nbase, t);
        mma_chunk<132>(Xs, buf, m0w, n0w, g, tg, k0 * 32, acc);
    }
}

// ---------------- 0. meta-MLP relative position bias ----------------
__global__ void __launch_bounds__(256) bias_kernel(const float* __restrict__ w1, const float* __restrict__ b1,
                                                   const float* __restrict__ w2, const float* __restrict__ b2) {
    __shared__ float sw1[512], sb1[256], sw2[1024], sb2[4];
    int t = threadIdx.x;
    sw1[t] = w1[t]; sw1[256 + t] = w1[256 + t];
    sb1[t] = b1[t];
#pragma unroll
    for (int i = 0; i < 4; i++) sw2[i * 256 + t] = w2[i * 256 + t];
    if (t < 4) sb2[t] = b2[t];
    __syncthreads();

    int p = blockIdx.x * 256 + t;
    int q = p >> 6, k = p & 63;
    float dy = (float)((q >> 3) - (k >> 3));
    float dx = (float)((q & 7) - (k & 7));
    float r0 = copysignf(log1pf(fabsf(dy)), dy);
    float r1 = copysignf(log1pf(fabsf(dx)), dx);
    float a0 = 0.f, a1 = 0.f, a2 = 0.f, a3 = 0.f;
#pragma unroll 8
    for (int j = 0; j < 256; j++) {
        float h = fmaxf(r0 * sw1[j] + r1 * sw1[256 + j] + sb1[j], 0.f);
        a0 += h * sw2[j * 4 + 0];
        a1 += h * sw2[j * 4 + 1];
        a2 += h * sw2[j * 4 + 2];
        a3 += h * sw2[j * 4 + 3];
    }
    g_bias[0 * 4096 + p] = a0 + sb2[0];
    g_bias[1 * 4096 + p] = a1 + sb2[1];
    g_bias[2 * 4096 + p] = a2 + sb2[2];
    g_bias[3 * 4096 + p] = a3 + sb2[3];
}

// ---------------- 1. QKV: fused roll+gather (A resident) + pipelined GEMM ----------------
__global__ void __launch_bounds__(256) qkv_mma(const float* __restrict__ x,
                                               const float* __restrict__ w,
                                               const float* __restrict__ qb) {
    extern __shared__ __align__(16) unsigned char sm[];
    uint32_t* Xs = (uint32_t*)sm;             // [64][132]
    uint32_t* Bs = (uint32_t*)(sm + 33792);   // 2 chunks

    int t = threadIdx.x;
    int win = blockIdx.x;
    int b = win >> 6, wy = (win >> 3) & 7, wx = win & 7;

    const int lane = t & 31, g = lane >> 2, tg = lane & 3;
    const int warp = t >> 5;
    const int wm = warp & 3, wn = warp >> 2;
    const int m0w = wm * 16, n0w = wn * 64;

    // gather x (roll -SHIFT) -> Xs tf32 (transposed: [tok][c])
#pragma unroll
    for (int it = 0; it < 8; it++) {
        int p = it * 256 + t;
        int c = p >> 4;
        int r = (p >> 1) & 7;
        int half = p & 1;
        int y  = (wy * 8 + r + 4) & 63;
        int xb = (wx * 8 + 4 + half * 4) & 63;
        float4 v = *(const float4*)&x[((size_t)(b * 128 + c) * 64 + y) * 64 + xb];
        int tok = r * 8 + half * 4;
        Xs[(tok + 0) * 132 + c] = f2tf32(v.x);
        Xs[(tok + 1) * 132 + c] = f2tf32(v.y);
        Xs[(tok + 2) * 132 + c] = f2tf32(v.z);
        Xs[(tok + 3) * 132 + c] = f2tf32(v.w);
    }

    for (int nb = 0; nb < 3; nb++) {
        float acc[8][4] = {};
        gemm_ares(Xs, Bs, w, 384, nb * 128, m0w, n0w, g, tg, t, acc);

        float* dst = (nb == 0) ? g_q : (nb == 1) ? g_k : g_v;
#pragma unroll
        for (int s = 0; s < 8; s++) {
            int nl = n0w + s * 8 + 2 * tg;
            int head = nl >> 5, d = nl & 31;
            float b0v = qb[nb * 128 + nl], b1v = qb[nb * 128 + nl + 1];
            int m = m0w + g;
            float* base = &dst[((size_t)(win * 4 + head) * 64 + m) * 32 + d];
            *(float2*)base = make_float2(acc[s][0] + b0v, acc[s][1] + b1v);
            *(float2*)(base + 8 * 32) = make_float2(acc[s][2] + b0v, acc[s][3] + b1v);
        }
    }
}

// ---------------- 2. windowed attention (tf32 mma) ----------------
__global__ void __launch_bounds__(128) attn_mma(const float* __restrict__ tau) {
    __shared__ __align__(16) uint32_t Qs[64 * 36];
    __shared__ __align__(16) uint32_t Ks[64 * 36];
    __shared__ __align__(16) uint32_t Vs[64 * 36];
    __shared__ __align__(16) uint32_t Ps[64 * 68];
    __shared__ float qn[64], kn[64];
    __shared__ int   cnti[64];
    __shared__ float stau;

    int t = threadIdx.x;
    int wh = blockIdx.x;
    int win = wh >> 2, h = wh & 3;
    int wy = (win >> 3) & 7, wx = win & 7;

    const float* qp = g_q + (size_t)wh * 2048;
    const float* kp = g_k + (size_t)wh * 2048;
    const float* vp = g_v + (size_t)wh * 2048;

    for (int it = 0; it < 16; it++) {
        int idx = it * 128 + t;
        int tok = idx >> 5, d = idx & 31;
        Qs[tok * 36 + d] = f2tf32(qp[idx]);
        Ks[tok * 36 + d] = f2tf32(kp[idx]);
        Vs[tok * 36 + d] = f2tf32(vp[idx]);
    }
    if (t < 64) {
        int ys = wy * 8 + (t >> 3);
        int xs = wx * 8 + (t & 7);
        int ry = ys < 56 ? 0 : (ys < 60 ? 1 : 2);
        int rx = xs < 56 ? 0 : (xs < 60 ? 1 : 2);
        cnti[t] = ry * 3 + rx;
    }
    if (t == 0) stau = fmaxf(tau[h], 0.01f);
    {
        const float* rp = (t < 64) ? (qp + t * 32) : (kp + (t - 64) * 32);
        float s = 0.f;
#pragma unroll
        for (int d4 = 0; d4 < 8; d4++) {
            float4 v = *(const float4*)&rp[d4 * 4];
            s += v.x * v.x + v.y * v.y + v.z * v.z + v.w * v.w;
        }
        float nv = sqrtf(s);
        if (t < 64) qn[t] = nv; else kn[t - 64] = nv;
    }
    __syncthreads();

    const int lane = t & 31, g = lane >> 2, tg = lane & 3;
    const int wid = t >> 5;
    const int m0 = wid * 16;
    const int r0 = m0 + g, r1 = r0 + 8;

    float acc[8][4] = {};
#pragma unroll
    for (int ks = 0; ks < 4; ks++) {
        int kk = ks * 8;
        uint32_t a0 = Qs[r0 * 36 + kk + tg];
        uint32_t a1 = Qs[r1 * 36 + kk + tg];
        uint32_t a2 = Qs[r0 * 36 + kk + tg + 4];
        uint32_t a3 = Qs[r1 * 36 + kk + tg + 4];
#pragma unroll
        for (int s = 0; s < 8; s++) {
            uint32_t b0 = Ks[(s * 8 + g) * 36 + kk + tg];
            uint32_t b1 = Ks[(s * 8 + g) * 36 + kk + tg + 4];
            mma8(acc[s], a0, a1, a2, a3, b0, b1);
        }
    }

    float tv = stau;
    float qn0 = qn[r0], qn1 = qn[r1];
    int mq0 = cnti[r0], mq1 = cnti[r1];
    const float* bias0 = &g_bias[h * 4096 + r0 * 64];
    const float* bias1 = &g_bias[h * 4096 + r1 * 64];
#pragma unroll
    for (int s = 0; s < 8; s++) {
        int c0 = s * 8 + 2 * tg;
        float kn0 = kn[c0], kn1 = kn[c0 + 1];
        float2 bA = *(const float2*)&bias0[c0];
        float2 bB = *(const float2*)&bias1[c0];
        int mk0 = cnti[c0], mk1 = cnti[c0 + 1];
        acc[s][0] = acc[s][0] / fmaxf(qn0 * kn0, 1e-6f) / tv + bA.x + (mq0 != mk0 ? -100.f : 0.f);
        acc[s][1] = acc[s][1] / fmaxf(qn0 * kn1, 1e-6f) / tv + bA.y + (mq0 != mk1 ? -100.f : 0.f);
        acc[s][2] = acc[s][2] / fmaxf(qn1 * kn0, 1e-6f) / tv + bB.x + (mq1 != mk0 ? -100.f : 0.f);
        acc[s][3] = acc[s][3] / fmaxf(qn1 * kn1, 1e-6f) / tv + bB.y + (mq1 != mk1 ? -100.f : 0.f);
    }

    float mx0 = -1e30f, mx1 = -1e30f;
#pragma unroll
    for (int s = 0; s < 8; s++) {
        mx0 = fmaxf(mx0, fmaxf(acc[s][0], acc[s][1]));
        mx1 = fmaxf(mx1, fmaxf(acc[s][2], acc[s][3]));
    }
#pragma unroll
    for (int o = 1; o <= 2; o <<= 1) {
        mx0 = fmaxf(mx0, __shfl_xor_sync(0xffffffffu, mx0, o));
        mx1 = fmaxf(mx1, __shfl_xor_sync(0xffffffffu, mx1, o));
    }
    float sm0 = 0.f, sm1 = 0.f;
#pragma unroll
    for (int s = 0; s < 8; s++) {
        acc[s][0] = expf(acc[s][0] - mx0);
        acc[s][1] = expf(acc[s][1] - mx0);
        acc[s][2] = expf(acc[s][2] - mx1);
        acc[s][3] = expf(acc[s][3] - mx1);
        sm0 += acc[s][0] + acc[s][1];
        sm1 += acc[s][2] + acc[s][3];
    }
#pragma unroll
    for (int o = 1; o <= 2; o <<= 1) {
        sm0 += __shfl_xor_sync(0xffffffffu, sm0, o);
        sm1 += __shfl_xor_sync(0xffffffffu, sm1, o);
    }
    float inv0 = 1.f / sm0, inv1 = 1.f / sm1;
#pragma unroll
    for (int s = 0; s < 8; s++) {
        int c0 = s * 8 + 2 * tg;
        Ps[r0 * 68 + c0]     = f2tf32(acc[s][0] * inv0);
        Ps[r0 * 68 + c0 + 1] = f2tf32(acc[s][1] * inv0);
        Ps[r1 * 68 + c0]     = f2tf32(acc[s][2] * inv1);
        Ps[r1 * 68 + c0 + 1] = f2tf32(acc[s][3] * inv1);
    }
    __syncwarp();

    float oacc[4][4] = {};
#pragma unroll
    for (int ks = 0; ks < 8; ks++) {
        int kk = ks * 8;
        uint32_t a0 = Ps[r0 * 68 + kk + tg];
        uint32_t a1 = Ps[r1 * 68 + kk + tg];
        uint32_t a2 = Ps[r0 * 68 + kk + tg + 4];
        uint32_t a3 = Ps[r1 * 68 + kk + tg + 4];
#pragma unroll
        for (int s2 = 0; s2 < 4; s2++) {
            uint32_t b0 = Vs[(kk + tg) * 36 + s2 * 8 + g];
            uint32_t b1 = Vs[(kk + tg + 4) * 36 + s2 * 8 + g];
            mma8(oacc[s2], a0, a1, a2, a3, b0, b1);
        }
    }

#pragma unroll
    for (int s2 = 0; s2 < 4; s2++) {
        int dc = s2 * 8 + 2 * tg;
        *(float2*)&g_attn[((size_t)win * 64 + r0) * 128 + h * 32 + dc] = make_float2(oacc[s2][0], oacc[s2][1]);
        *(float2*)&g_attn[((size_t)win * 64 + r1) * 128 + h * 32 + dc] = make_float2(oacc[s2][2], oacc[s2][3]);
    }
}

// ---------------- 3. proj (A resident, pipelined) + LN1 + residual -> g_skip ----------------
__global__ void __launch_bounds__(256) proj_mma(const float* __restrict__ x,
                                                const float* __restrict__ w,
                                                const float* __restrict__ pb,
                                                const float* __restrict__ lg,
                                                const float* __restrict__ lb) {
    extern __shared__ __align__(16) unsigned char sm[];
    uint32_t* Xs = (uint32_t*)sm;
    uint32_t* Bs = (uint32_t*)(sm + 33792);
    float* Cs = (float*)sm;

    int t = threadIdx.x;
    int win = blockIdx.x;
    int b = win >> 6, wy = (win >> 3) & 7, wx = win & 7;

    const int lane = t & 31, g = lane >> 2, tg = lane & 3;
    const int warp = t >> 5;
    const int wm = warp & 3, wn = warp >> 2;
    const int m0w = wm * 16, n0w = wn * 64;

    const float* ap = g_attn + (size_t)win * 64 * 128;
#pragma unroll
    for (int it = 0; it < 8; it++) {
        int p = it * 256 + t;
        int tok = p >> 5, c4 = p & 31;
        float4 v = *(const float4*)&ap[tok * 128 + c4 * 4];
        Xs[tok * 132 + c4 * 4 + 0] = f2tf32(v.x);
        Xs[tok * 132 + c4 * 4 + 1] = f2tf32(v.y);
        Xs[tok * 132 + c4 * 4 + 2] = f2tf32(v.z);
        Xs[tok * 132 + c4 * 4 + 3] = f2tf32(v.w);
    }

    float acc[8][4] = {};
    gemm_ares(Xs, Bs, w, 128, 0, m0w, n0w, g, tg, t, acc);

    __syncthreads();   // all MMA reads of Xs done before overwrite as Cs
#pragma unroll
    for (int s = 0; s < 8; s++) {
        int c = n0w + s * 8 + 2 * tg;
        float b0v = pb[c], b1v = pb[c + 1];
        Cs[(m0w + g) * 132 + c]         = acc[s][0] + b0v;
        Cs[(m0w + g) * 132 + c + 1]     = acc[s][1] + b1v;
        Cs[(m0w + g + 8) * 132 + c]     = acc[s][2] + b0v;
        Cs[(m0w + g + 8) * 132 + c + 1] = acc[s][3] + b1v;
    }
    __syncthreads();

    float4 lg4 = *(const float4*)&lg[lane * 4];
    float4 lb4 = *(const float4*)&lb[lane * 4];
    for (int i = 0; i < 8; i++) {
        int tk = warp * 8 + i;
        float4 v = *(const float4*)&Cs[tk * 132 + lane * 4];
        float s  = v.x + v.y + v.z + v.w;
        float ss = v.x * v.x + v.y * v.y + v.z * v.z + v.w * v.w;
#pragma unroll
        for (int o = 16; o; o >>= 1) {
            s  += __shfl_xor_sync(0xffffffffu, s, o);
            ss += __shfl_xor_sync(0xffffffffu, ss, o);
        }
        float mu = s * (1.f / 128.f);
        float var = ss * (1.f / 128.f) - mu * mu;
        float rs = rsqrtf(var + 1e-5f);

        int y  = (wy * 8 + (tk >> 3) + 4) & 63;
        int xx = (wx * 8 + (tk & 7) + 4) & 63;
        const float* xr = x + ((size_t)(b * 128 + lane * 4) * 64 + y) * 64 + xx;
        float4 o4;
        o4.x = (v.x - mu) * rs * lg4.x + lb4.x + xr[0];
        o4.y = (v.y - mu) * rs * lg4.y + lb4.y + xr[4096];
        o4.z = (v.z - mu) * rs * lg4.z + lb4.z + xr[8192];
        o4.w = (v.w - mu) * rs * lg4.w + lb4.w + xr[12288];
        *(float4*)&g_skip[((size_t)b * 4096 + y * 64 + xx) * 128 + lane * 4] = o4;
    }
}

// ---------------- 4. FFN1 (A resident, pipelined, 4 N-blocks) + GELU -> g_h1 ----------------
__global__ void __launch_bounds__(256) ffn1_mma(const float* __restrict__ w,
                                                const float* __restrict__ b1) {
    extern __shared__ __align__(16) unsigned char sm[];
    uint32_t* Xs = (uint32_t*)sm;
    uint32_t* Bs = (uint32_t*)(sm + 33792);

    int t = threadIdx.x;
    int tile = blockIdx.x;

    const int lane = t & 31, g = lane >> 2, tg = lane & 3;
    const int warp = t >> 5;
    const int wm = warp & 3, wn = warp >> 2;
    const int m0w = wm * 16, n0w = wn * 64;

    const float* sp = g_skip + (size_t)tile * 64 * 128;
#pragma unroll
    for (int it = 0; it < 8; it++) {
        int p = it * 256 + t;
        int tok = p >> 5, c4 = p & 31;
        float4 v = *(const float4*)&sp[tok * 128 + c4 * 4];
        Xs[tok * 132 + c4 * 4 + 0] = f2tf32(v.x);
        Xs[tok * 132 + c4 * 4 + 1] = f2tf32(v.y);
        Xs[tok * 132 + c4 * 4 + 2] = f2tf32(v.z);
        Xs[tok * 132 + c4 * 4 + 3] = f2tf32(v.w);
    }

    for (int nb = 0; nb < 4; nb++) {
        float acc[8][4] = {};
        gemm_ares(Xs, Bs, w, 512, nb * 128, m0w, n0w, g, tg, t, acc);

        int r0 = m0w + g, r1 = r0 + 8;
#pragma unroll
        for (int s = 0; s < 8; s++) {
            int nl = n0w + s * 8 + 2 * tg;
            int ng = nb * 128 + nl;
            float b0v = b1[ng], b1v = b1[ng + 1];
            float h0 = acc[s][0] + b0v, h1 = acc[s][1] + b1v;
            float h2 = acc[s][2] + b0v, h3 = acc[s][3] + b1v;
            h0 = 0.5f * h0 * (1.f + erff(h0 * 0.70710678118654752f));
            h1 = 0.5f * h1 * (1.f + erff(h1 * 0.70710678118654752f));
            h2 = 0.5f * h2 * (1.f + erff(h2 * 0.70710678118654752f));
            h3 = 0.5f * h3 * (1.f + erff(h3 * 0.70710678118654752f));
            float* base = &g_h1[((size_t)tile * 64 + r0) * 512 + ng];
            *(float2*)base = make_float2(h0, h1);
            *(float2*)(base + 8 * 512) = make_float2(h2, h3);
        }
    }
}

// ---------------- 5. FFN2 (K=512, A+B double-buffered) + LN2 + residual -> out ----------------
__global__ void __launch_bounds__(256) ffn2_mma(const float* __restrict__ w,
                                                const float* __restrict__ b2,
                                                const float* __restrict__ lg,
                                                const float* __restrict__ lb,
                                                float* __restrict__ out) {
    extern __shared__ __align__(16) unsigned char sm[];
    uint32_t* As = (uint32_t*)sm;               // 2 x [64][36]
    uint32_t* Bs = (uint32_t*)(sm + 18432);     // 2 x [32][136]
    float* Cs = (float*)sm;                     // epilogue reuse (33792 B < 53248)

    int t = threadIdx.x;
    int tile = blockIdx.x;

    const int lane = t & 31, g = lane >> 2, tg = lane & 3;
    const int warp = t >> 5;
    const int wm = warp & 3, wn = warp >> 2;
    const int m0w = wm * 16, n0w = wn * 64;

    const float* hp = g_h1 + (size_t)tile * 64 * 512;

    float4 pfB[4];
    float4 pfA[2];
    pf_b(pfB, w, 0, 128, 0, t);
#pragma unroll
    for (int it = 0; it < 2; it++) {
        int p = it * 256 + t;
        int tok = p >> 3, k4 = p & 7;
        pfA[it] = *(const float4*)&hp[tok * 512 + k4 * 4];
    }

    float acc[8][4] = {};
    for (int k0 = 0; k0 < 16; k0++) {
        uint32_t* bufA = As + (k0 & 1) * 2304;
        uint32_t* bufB = Bs + (k0 & 1) * BCH;
        st_b(bufB, pfB, t);
#pragma unroll
        for (int it = 0; it < 2; it++) {
            int p = it * 256 + t;
            int tok = p >> 3, k4 = p & 7;
            *(uint4*)&bufA[tok * 36 + k4 * 4] =
                make_uint4(f2tf32(pfA[it].x), f2tf32(pfA[it].y), f2tf32(pfA[it].z), f2tf32(pfA[it].w));
        }
        __syncthreads();
        if (k0 < 15) {
            pf_b(pfB, w, (k0 + 1) * 32, 128, 0, t);
#pragma unroll
            for (int it = 0; it < 2; it++) {
                int p = it * 256 + t;
                int tok = p >> 3, k4 = p & 7;
                pfA[it] = *(const float4*)&hp[tok * 512 + (k0 + 1) * 32 + k4 * 4];
            }
        }
        mma_chunk<36>(bufA, bufB, m0w, n0w, g, tg, 0, acc);
    }

    __syncthreads();
#pragma unroll
    for (int s = 0; s < 8; s++) {
        int c = n0w + s * 8 + 2 * tg;
        float b0v = b2[c], b1v = b2[c + 1];
        Cs[(m0w + g) * 132 + c]         = acc[s][0] + b0v;
        Cs[(m0w + g) * 132 + c + 1]     = acc[s][1] + b1v;
        Cs[(m0w + g + 8) * 132 + c]     = acc[s][2] + b0v;
        Cs[(m0w + g + 8) * 132 + c + 1] = acc[s][3] + b1v;
    }
    __syncthreads();

    const float* sp = g_skip + (size_t)tile * 64 * 128;
    float4 lg4 = *(const float4*)&lg[lane * 4];
    float4 lb4 = *(const float4*)&lb[lane * 4];
    for (int i = 0; i < 8; i++) {
        int tk = warp * 8 + i;
        float4 v = *(const float4*)&Cs[tk * 132 + lane * 4];
        float s  = v.x + v.y + v.z + v.w;
        float ss = v.x * v.x + v.y * v.y + v.z * v.z + v.w * v.w;
#pragma unroll
        for (int o = 16; o; o >>= 1) {
            s  += __shfl_xor_sync(0xffffffffu, s, o);
            ss += __shfl_xor_sync(0xffffffffu, ss, o);
        }
        float mu = s * (1.f / 128.f);
        float var = ss * (1.f / 128.f) - mu * mu;
        float rs = rsqrtf(var + 1e-5f);
        float4 sk = *(const float4*)&sp[tk * 128 + lane * 4];
        float4 o4;
        o4.x = (v.x - mu) * rs * lg4.x + lb4.x + sk.x;
        o4.y = (v.y - mu) * rs * lg4.y + lb4.y + sk.y;
        o4.z = (v.z - mu) * rs * lg4.z + lb4.z + sk.z;
        o4.w = (v.w - mu) * rs * lg4.w + lb4.w + sk.w;
        *(float4*)&Cs[tk * 132 + lane * 4] = o4;
    }
    __syncthreads();

    int b = tile >> 6, y = tile & 63;
    for (int it = 0; it < 32; it++) {
        int idx = it * 256 + t;
        int c = idx >> 6, xcol = idx & 63;
        out[((size_t)(b * 128 + c) * 64 + y) * 64 + xcol] = Cs[xcol * 132 + c];
    }
}

// ---------------- launch ----------------
extern "C" void kernel_launch(void* const* d_in, const int* in_sizes, int n_in,
                              void* d_out, int out_size) {
    (void)in_sizes; (void)n_in; (void)out_size;
    const float* x      = (const float*)d_in[0];
    const float* qkv_w  = (const float*)d_in[1];
    const float* qkv_b  = (const float*)d_in[2];
    const float* proj_w = (const float*)d_in[3];
    const float* proj_b = (const float*)d_in[4];
    const float* mw1    = (const float*)d_in[5];
    const float* mb1    = (const float*)d_in[6];
    const float* mw2    = (const float*)d_in[7];
    const float* mb2    = (const float*)d_in[8];
    const float* tau    = (const float*)d_in[9];
    const float* ln1_g  = (const float*)d_in[10];
    const float* ln1_b  = (const float*)d_in[11];
    const float* ln2_g  = (const float*)d_in[12];
    const float* ln2_b  = (const float*)d_in[13];
    const float* ffn_w1 = (const float*)d_in[14];
    const float* ffn_b1 = (const float*)d_in[15];
    const float* ffn_w2 = (const float*)d_in[16];
    const float* ffn_b2 = (const float*)d_in[17];
    float* out = (float*)d_out;

    cudaFuncSetAttribute(qkv_mma,  cudaFuncAttributeMaxDynamicSharedMemorySize, SMEM_ARES);
    cudaFuncSetAttribute(proj_mma, cudaFuncAttributeMaxDynamicSharedMemorySize, SMEM_ARES);
    cudaFuncSetAttribute(ffn1_mma, cudaFuncAttributeMaxDynamicSharedMemorySize, SMEM_ARES);
    cudaFuncSetAttribute(ffn2_mma, cudaFuncAttributeMaxDynamicSharedMemorySize, SMEM_FFN2);

    bias_kernel<<<16, 256>>>(mw1, mb1, mw2, mb2);
    qkv_mma<<<N_WIN, 256, SMEM_ARES>>>(x, qkv_w, qkv_b);
    attn_mma<<<8192, 128>>>(tau);
    proj_mma<<<N_WIN, 256, SMEM_ARES>>>(x, proj_w, proj_b, ln1_g, ln1_b);
    ffn1_mma<<<N_WIN, 256, SMEM_ARES>>>(ffn_w1, ffn_b1);
    ffn2_mma<<<N_WIN, 256, SMEM_FFN2>>>(ffn_w2, ffn_b2, ln2_g, ln2_b, out);
}

// round 8
// speedup vs baseline: 1.3608x; 1.0299x over previous
#include <cuda_runtime.h>
#include <math.h>
#include <stdint.h>

// B=32, C=128, H=W=64, WS=8, SHIFT=4, HEADS=4, TOK=64, NW=64, DH=32, HID=512
#define N_WIN   2048
#define N_TOK   131072

// ---------------- scratch ----------------
__device__ float g_q[8192 * 2048];           // [win*4+h][tok=64][d=32]
__device__ float g_k[8192 * 2048];
__device__ float g_v[8192 * 2048];
__device__ float g_attn[N_WIN * 64 * 128];   // [win][tok][c]
__device__ float g_skip[N_TOK * 128];        // [tokg][c]
__device__ float g_h1[N_TOK * 512];          // [tokg][hid]
__device__ float g_bias[4 * 64 * 64];        // [h][q][k]

// ---------------- tf32 mma helpers ----------------
__device__ __forceinline__ uint32_t f2tf32(float x) {
    uint32_t r;
    asm("cvt.rna.tf32.f32 %0, %1;" : "=r"(r) : "f"(x));
    return r;
}

__device__ __forceinline__ void mma8(float c[4], uint32_t a0, uint32_t a1, uint32_t a2, uint32_t a3,
                                     uint32_t b0, uint32_t b1) {
    asm volatile("mma.sync.aligned.m16n8k8.row.col.f32.tf32.tf32.f32 "
                 "{%0,%1,%2,%3},{%4,%5,%6,%7},{%8,%9},{%0,%1,%2,%3};"
                 : "+f"(c[0]), "+f"(c[1]), "+f"(c[2]), "+f"(c[3])
                 : "r"(a0), "r"(a1), "r"(a2), "r"(a3), "r"(b0), "r"(b1));
}

// 32-K chunk of the 128x128 block tile; warp tile 32x64 (two stacked 16x64 groups).
// B fragments shared across both M-groups: ~1.5 LDS per MMA.
template<int ASTR>
__device__ __forceinline__ void mma_chunk2(const uint32_t* __restrict__ As, const uint32_t* __restrict__ Bs,
                                           int m0w, int n0w, int g, int tg, int kbase,
                                           float acc0[8][4], float acc1[8][4]) {
#pragma unroll
    for (int ks = 0; ks < 4; ks++) {
        int kk = kbase + ks * 8;
        int bk = ks * 8;
        uint32_t a00 = As[(m0w + g) * ASTR + kk + tg];
        uint32_t a01 = As[(m0w + g + 8) * ASTR + kk + tg];
        uint32_t a02 = As[(m0w + g) * ASTR + kk + tg + 4];
        uint32_t a03 = As[(m0w + g + 8) * ASTR + kk + tg + 4];
        uint32_t a10 = As[(m0w + 16 + g) * ASTR + kk + tg];
        uint32_t a11 = As[(m0w + 24 + g) * ASTR + kk + tg];
        uint32_t a12 = As[(m0w + 16 + g) * ASTR + kk + tg + 4];
        uint32_t a13 = As[(m0w + 24 + g) * ASTR + kk + tg + 4];
#pragma unroll
        for (int s = 0; s < 8; s++) {
            uint32_t b0 = Bs[(bk + tg) * 136 + n0w + s * 8 + g];
            uint32_t b1 = Bs[(bk + tg + 4) * 136 + n0w + s * 8 + g];
            mma8(acc0[s], a00, a01, a02, a03, b0, b1);
            mma8(acc1[s], a10, a11, a12, a13, b0, b1);
        }
    }
}

// prefetch a 32x128 weight chunk into registers (256 threads, 4 float4 each)
__device__ __forceinline__ void pf_b(float4 r[4], const float* __restrict__ W,
                                     int row0, int WSTR, int ncol0, int t) {
#pragma unroll
    for (int it = 0; it < 4; it++) {
        int p = it * 256 + t;
        int k = p >> 5, n4 = p & 31;
        r[it] = *(const float4*)&W[(size_t)(row0 + k) * WSTR + ncol0 + n4 * 4];
    }
}
__device__ __forceinline__ void st_b(uint32_t* __restrict__ Bs, const float4 r[4], int t) {
#pragma unroll
    for (int it = 0; it < 4; it++) {
        int p = it * 256 + t;
        int k = p >> 5, n4 = p & 31;
        *(uint4*)&Bs[k * 136 + n4 * 4] =
            make_uint4(f2tf32(r[it].x), f2tf32(r[it].y), f2tf32(r[it].z), f2tf32(r[it].w));
    }
}

#define BCH 4352                 // words per Bs chunk (32*136)
#define SMEM_ARES 102400         // Xs 128*132*4 + 2*17408
#define SMEM_FFN2 71680          // 2*18432 (As) + 2*17408 (Bs)

// A-resident (Xs[128][132]) pipelined GEMM over one 128-col N-block, K=128
__device__ __forceinline__ void gemm_ares2(const uint32_t* __restrict__ Xs, uint32_t* __restrict__ Bs,
                                           const float* __restrict__ W, int WSTR, int nbase,
                                           int m0w, int n0w, int g, int tg, int t,
                                           float acc0[8][4], float acc1[8][4]) {
    float4 pf[4];
    pf_b(pf, W, 0, WSTR, nbase, t);
#pragma unroll
    for (int k0 = 0; k0 < 4; k0++) {
        uint32_t* buf = Bs + (k0 & 1) * BCH;
        st_b(buf, pf, t);
        __syncthreads();
        if (k0 < 3) pf_b(pf, W, (k0 + 1) * 32, WSTR, nbase, t);
        mma_chunk2<132>(Xs, buf, m0w, n0w, g, tg, k0 * 32, acc0, acc1);
    }
}

// ---------------- 0. meta-MLP relative position bias (one output/thread) ----------------
__global__ void __launch_bounds__(256) bias_kernel(const float* __restrict__ w1, const float* __restrict__ b1,
                                                   const float* __restrict__ w2, const float* __restrict__ b2) {
    __shared__ float sw1[512], sb1[256], sw2[1024], sb2[4];
    int t = threadIdx.x;
    sw1[t] = w1[t]; sw1[256 + t] = w1[256 + t];
    sb1[t] = b1[t];
#pragma unroll
    for (int i = 0; i < 4; i++) sw2[i * 256 + t] = w2[i * 256 + t];
    if (t < 4) sb2[t] = b2[t];
    __syncthreads();

    int o = blockIdx.x * 256 + t;       // 64 blocks -> 16384 outputs
    int p = o >> 2, head = o & 3;
    int q = p >> 6, k = p & 63;
    float dy = (float)((q >> 3) - (k >> 3));
    float dx = (float)((q & 7) - (k & 7));
    float r0 = copysignf(log1pf(fabsf(dy)), dy);
    float r1 = copysignf(log1pf(fabsf(dx)), dx);
    float a = 0.f;
#pragma unroll 8
    for (int j = 0; j < 256; j++) {
        float h = fmaxf(r0 * sw1[j] + r1 * sw1[256 + j] + sb1[j], 0.f);
        a += h * sw2[j * 4 + head];
    }
    g_bias[head * 4096 + p] = a + sb2[head];
}

// ---------------- 1. QKV: 2 windows/block, fused roll+gather, pipelined ----------------
__global__ void __launch_bounds__(256) qkv_mma(const float* __restrict__ x,
                                               const float* __restrict__ w,
                                               const float* __restrict__ qb) {
    extern __shared__ __align__(16) unsigned char sm[];
    uint32_t* Xs = (uint32_t*)sm;             // [128][132]
    uint32_t* Bs = (uint32_t*)(sm + 67584);   // 2 chunks

    int t = threadIdx.x;
    int win0 = blockIdx.x * 2;
    int b = win0 >> 6;

    const int lane = t & 31, g = lane >> 2, tg = lane & 3;
    const int warp = t >> 5;
    const int wm = warp & 3, wn = warp >> 2;
    const int m0w = wm * 32, n0w = wn * 64;

    // gather 2 windows (roll -SHIFT) -> Xs tf32 [row=wl*64+tok][c]
#pragma unroll
    for (int it = 0; it < 16; it++) {
        int p = it * 256 + t;
        int wl = p >> 11;
        int q = p & 2047;
        int c = q >> 4;
        int r = (q >> 1) & 7;
        int half = q & 1;
        int win = win0 + wl;
        int wy = (win >> 3) & 7, wx = win & 7;
        int y  = (wy * 8 + r + 4) & 63;
        int xb = (wx * 8 + 4 + half * 4) & 63;
        float4 v = *(const float4*)&x[((size_t)(b * 128 + c) * 64 + y) * 64 + xb];
        int row = wl * 64 + r * 8 + half * 4;
        Xs[(row + 0) * 132 + c] = f2tf32(v.x);
        Xs[(row + 1) * 132 + c] = f2tf32(v.y);
        Xs[(row + 2) * 132 + c] = f2tf32(v.z);
        Xs[(row + 3) * 132 + c] = f2tf32(v.w);
    }

    for (int nb = 0; nb < 3; nb++) {
        float acc0[8][4] = {}, acc1[8][4] = {};
        gemm_ares2(Xs, Bs, w, 384, nb * 128, m0w, n0w, g, tg, t, acc0, acc1);

        float* dst = (nb == 0) ? g_q : (nb == 1) ? g_k : g_v;
#pragma unroll
        for (int mi = 0; mi < 2; mi++) {
            float (*ac)[4] = mi ? acc1 : acc0;
            int r0 = m0w + mi * 16 + g;
            int win = win0 + (r0 >> 6);
            int tok = r0 & 63;
#pragma unroll
            for (int s = 0; s < 8; s++) {
                int nl = n0w + s * 8 + 2 * tg;
                int head = nl >> 5, d = nl & 31;
                float b0v = qb[nb * 128 + nl], b1v = qb[nb * 128 + nl + 1];
                float* base = &dst[((size_t)(win * 4 + head) * 64 + tok) * 32 + d];
                *(float2*)base = make_float2(ac[s][0] + b0v, ac[s][1] + b1v);
                *(float2*)(base + 8 * 32) = make_float2(ac[s][2] + b0v, ac[s][3] + b1v);
            }
        }
    }
}

// ---------------- 2. windowed attention (tf32 mma) ----------------
__global__ void __launch_bounds__(128) attn_mma(const float* __restrict__ tau) {
    __shared__ __align__(16) uint32_t Qs[64 * 36];
    __shared__ __align__(16) uint32_t Ks[64 * 36];
    __shared__ __align__(16) uint32_t Vs[64 * 36];
    __shared__ __align__(16) uint32_t Ps[64 * 68];
    __shared__ float qn[64], kn[64];
    __shared__ int   cnti[64];
    __shared__ float stau;

    int t = threadIdx.x;
    int wh = blockIdx.x;
    int win = wh >> 2, h = wh & 3;
    int wy = (win >> 3) & 7, wx = win & 7;

    const float* qp = g_q + (size_t)wh * 2048;
    const float* kp = g_k + (size_t)wh * 2048;
    const float* vp = g_v + (size_t)wh * 2048;

    for (int it = 0; it < 16; it++) {
        int idx = it * 128 + t;
        int tok = idx >> 5, d = idx & 31;
        Qs[tok * 36 + d] = f2tf32(qp[idx]);
        Ks[tok * 36 + d] = f2tf32(kp[idx]);
        Vs[tok * 36 + d] = f2tf32(vp[idx]);
    }
    if (t < 64) {
        int ys = wy * 8 + (t >> 3);
        int xs = wx * 8 + (t & 7);
        int ry = ys < 56 ? 0 : (ys < 60 ? 1 : 2);
        int rx = xs < 56 ? 0 : (xs < 60 ? 1 : 2);
        cnti[t] = ry * 3 + rx;
    }
    if (t == 0) stau = fmaxf(tau[h], 0.01f);
    {
        const float* rp = (t < 64) ? (qp + t * 32) : (kp + (t - 64) * 32);
        float s = 0.f;
#pragma unroll
        for (int d4 = 0; d4 < 8; d4++) {
            float4 v = *(const float4*)&rp[d4 * 4];
            s += v.x * v.x + v.y * v.y + v.z * v.z + v.w * v.w;
        }
        float nv = sqrtf(s);
        if (t < 64) qn[t] = nv; else kn[t - 64] = nv;
    }
    __syncthreads();

    const int lane = t & 31, g = lane >> 2, tg = lane & 3;
    const int wid = t >> 5;
    const int m0 = wid * 16;
    const int r0 = m0 + g, r1 = r0 + 8;

    float acc[8][4] = {};
#pragma unroll
    for (int ks = 0; ks < 4; ks++) {
        int kk = ks * 8;
        uint32_t a0 = Qs[r0 * 36 + kk + tg];
        uint32_t a1 = Qs[r1 * 36 + kk + tg];
        uint32_t a2 = Qs[r0 * 36 + kk + tg + 4];
        uint32_t a3 = Qs[r1 * 36 + kk + tg + 4];
#pragma unroll
        for (int s = 0; s < 8; s++) {
            uint32_t b0 = Ks[(s * 8 + g) * 36 + kk + tg];
            uint32_t b1 = Ks[(s * 8 + g) * 36 + kk + tg + 4];
            mma8(acc[s], a0, a1, a2, a3, b0, b1);
        }
    }

    float tv = stau;
    float qn0 = qn[r0], qn1 = qn[r1];
    int mq0 = cnti[r0], mq1 = cnti[r1];
    const float* bias0 = &g_bias[h * 4096 + r0 * 64];
    const float* bias1 = &g_bias[h * 4096 + r1 * 64];
#pragma unroll
    for (int s = 0; s < 8; s++) {
        int c0 = s * 8 + 2 * tg;
        float kn0 = kn[c0], kn1 = kn[c0 + 1];
        float2 bA = *(const float2*)&bias0[c0];
        float2 bB = *(const float2*)&bias1[c0];
        int mk0 = cnti[c0], mk1 = cnti[c0 + 1];
        acc[s][0] = acc[s][0] / fmaxf(qn0 * kn0, 1e-6f) / tv + bA.x + (mq0 != mk0 ? -100.f : 0.f);
        acc[s][1] = acc[s][1] / fmaxf(qn0 * kn1, 1e-6f) / tv + bA.y + (mq0 != mk1 ? -100.f : 0.f);
        acc[s][2] = acc[s][2] / fmaxf(qn1 * kn0, 1e-6f) / tv + bB.x + (mq1 != mk0 ? -100.f : 0.f);
        acc[s][3] = acc[s][3] / fmaxf(qn1 * kn1, 1e-6f) / tv + bB.y + (mq1 != mk1 ? -100.f : 0.f);
    }

    float mx0 = -1e30f, mx1 = -1e30f;
#pragma unroll
    for (int s = 0; s < 8; s++) {
        mx0 = fmaxf(mx0, fmaxf(acc[s][0], acc[s][1]));
        mx1 = fmaxf(mx1, fmaxf(acc[s][2], acc[s][3]));
    }
#pragma unroll
    for (int o = 1; o <= 2; o <<= 1) {
        mx0 = fmaxf(mx0, __shfl_xor_sync(0xffffffffu, mx0, o));
        mx1 = fmaxf(mx1, __shfl_xor_sync(0xffffffffu, mx1, o));
    }
    float sm0 = 0.f, sm1 = 0.f;
#pragma unroll
    for (int s = 0; s < 8; s++) {
        acc[s][0] = expf(acc[s][0] - mx0);
        acc[s][1] = expf(acc[s][1] - mx0);
        acc[s][2] = expf(acc[s][2] - mx1);
        acc[s][3] = expf(acc[s][3] - mx1);
        sm0 += acc[s][0] + acc[s][1];
        sm1 += acc[s][2] + acc[s][3];
    }
#pragma unroll
    for (int o = 1; o <= 2; o <<= 1) {
        sm0 += __shfl_xor_sync(0xffffffffu, sm0, o);
        sm1 += __shfl_xor_sync(0xffffffffu, sm1, o);
    }
    float inv0 = 1.f / sm0, inv1 = 1.f / sm1;
#pragma unroll
    for (int s = 0; s < 8; s++) {
        int c0 = s * 8 + 2 * tg;
        Ps[r0 * 68 + c0]     = f2tf32(acc[s][0] * inv0);
        Ps[r0 * 68 + c0 + 1] = f2tf32(acc[s][1] * inv0);
        Ps[r1 * 68 + c0]     = f2tf32(acc[s][2] * inv1);
        Ps[r1 * 68 + c0 + 1] = f2tf32(acc[s][3] * inv1);
    }
    __syncwarp();

    float oacc[4][4] = {};
#pragma unroll
    for (int ks = 0; ks < 8; ks++) {
        int kk = ks * 8;
        uint32_t a0 = Ps[r0 * 68 + kk + tg];
        uint32_t a1 = Ps[r1 * 68 + kk + tg];
        uint32_t a2 = Ps[r0 * 68 + kk + tg + 4];
        uint32_t a3 = Ps[r1 * 68 + kk + tg + 4];
#pragma unroll
        for (int s2 = 0; s2 < 4; s2++) {
            uint32_t b0 = Vs[(kk + tg) * 36 + s2 * 8 + g];
            uint32_t b1 = Vs[(kk + tg + 4) * 36 + s2 * 8 + g];
            mma8(oacc[s2], a0, a1, a2, a3, b0, b1);
        }
    }

#pragma unroll
    for (int s2 = 0; s2 < 4; s2++) {
        int dc = s2 * 8 + 2 * tg;
        *(float2*)&g_attn[((size_t)win * 64 + r0) * 128 + h * 32 + dc] = make_float2(oacc[s2][0], oacc[s2][1]);
        *(float2*)&g_attn[((size_t)win * 64 + r1) * 128 + h * 32 + dc] = make_float2(oacc[s2][2], oacc[s2][3]);
    }
}

// ---------------- 3. proj (2 windows/block) + LN1 + residual -> g_skip ----------------
__global__ void __launch_bounds__(256) proj_mma(const float* __restrict__ x,
                                                const float* __restrict__ w,
                                                const float* __restrict__ pb,
                                                const float* __restrict__ lg,
                                                const float* __restrict__ lb) {
    extern __shared__ __align__(16) unsigned char sm[];
    uint32_t* Xs = (uint32_t*)sm;
    uint32_t* Bs = (uint32_t*)(sm + 67584);
    float* Cs = (float*)sm;

    int t = threadIdx.x;
    int win0 = blockIdx.x * 2;
    int b = win0 >> 6;

    const int lane = t & 31, g = lane >> 2, tg = lane & 3;
    const int warp = t >> 5;
    const int wm = warp & 3, wn = warp >> 2;
    const int m0w = wm * 32, n0w = wn * 64;

    const float* ap = g_attn + (size_t)win0 * 64 * 128;   // 128 consecutive rows
#pragma unroll
    for (int it = 0; it < 16; it++) {
        int p = it * 256 + t;
        int row = p >> 5, c4 = p & 31;
        float4 v = *(const float4*)&ap[row * 128 + c4 * 4];
        Xs[row * 132 + c4 * 4 + 0] = f2tf32(v.x);
        Xs[row * 132 + c4 * 4 + 1] = f2tf32(v.y);
        Xs[row * 132 + c4 * 4 + 2] = f2tf32(v.z);
        Xs[row * 132 + c4 * 4 + 3] = f2tf32(v.w);
    }

    float acc0[8][4] = {}, acc1[8][4] = {};
    gemm_ares2(Xs, Bs, w, 128, 0, m0w, n0w, g, tg, t, acc0, acc1);

    __syncthreads();
#pragma unroll
    for (int mi = 0; mi < 2; mi++) {
        float (*ac)[4] = mi ? acc1 : acc0;
        int r0 = m0w + mi * 16 + g, r1 = r0 + 8;
#pragma unroll
        for (int s = 0; s < 8; s++) {
            int c = n0w + s * 8 + 2 * tg;
            float b0v = pb[c], b1v = pb[c + 1];
            Cs[r0 * 132 + c]     = ac[s][0] + b0v;
            Cs[r0 * 132 + c + 1] = ac[s][1] + b1v;
            Cs[r1 * 132 + c]     = ac[s][2] + b0v;
            Cs[r1 * 132 + c + 1] = ac[s][3] + b1v;
        }
    }
    __syncthreads();

    float4 lg4 = *(const float4*)&lg[lane * 4];
    float4 lb4 = *(const float4*)&lb[lane * 4];
    for (int i = 0; i < 16; i++) {
        int tk = warp * 16 + i;
        float4 v = *(const float4*)&Cs[tk * 132 + lane * 4];
        float s  = v.x + v.y + v.z + v.w;
        float ss = v.x * v.x + v.y * v.y + v.z * v.z + v.w * v.w;
#pragma unroll
        for (int o = 16; o; o >>= 1) {
            s  += __shfl_xor_sync(0xffffffffu, s, o);
            ss += __shfl_xor_sync(0xffffffffu, ss, o);
        }
        float mu = s * (1.f / 128.f);
        float var = ss * (1.f / 128.f) - mu * mu;
        float rs = rsqrtf(var + 1e-5f);

        int win = win0 + (tk >> 6);
        int wy = (win >> 3) & 7, wx = win & 7;
        int tokl = tk & 63;
        int y  = (wy * 8 + (tokl >> 3) + 4) & 63;
        int xx = (wx * 8 + (tokl & 7) + 4) & 63;
        const float* xr = x + ((size_t)(b * 128 + lane * 4) * 64 + y) * 64 + xx;
        float4 o4;
        o4.x = (v.x - mu) * rs * lg4.x + lb4.x + xr[0];
        o4.y = (v.y - mu) * rs * lg4.y + lb4.y + xr[4096];
        o4.z = (v.z - mu) * rs * lg4.z + lb4.z + xr[8192];
        o4.w = (v.w - mu) * rs * lg4.w + lb4.w + xr[12288];
        *(float4*)&g_skip[((size_t)b * 4096 + y * 64 + xx) * 128 + lane * 4] = o4;
    }
}

// ---------------- 4. FFN1 (128 tokens/block, 4 N-blocks) + GELU -> g_h1 ----------------
__global__ void __launch_bounds__(256) ffn1_mma(const float* __restrict__ w,
                                                const float* __restrict__ b1) {
    extern __shared__ __align__(16) unsigned char sm[];
    uint32_t* Xs = (uint32_t*)sm;
    uint32_t* Bs = (uint32_t*)(sm + 67584);

    int t = threadIdx.x;
    int tile = blockIdx.x;                    // 128 consecutive tokens

    const int lane = t & 31, g = lane >> 2, tg = lane & 3;
    const int warp = t >> 5;
    const int wm = warp & 3, wn = warp >> 2;
    const int m0w = wm * 32, n0w = wn * 64;

    const float* sp = g_skip + (size_t)tile * 128 * 128;
#pragma unroll
    for (int it = 0; it < 16; it++) {
        int p = it * 256 + t;
        int row = p >> 5, c4 = p & 31;
        float4 v = *(const float4*)&sp[row * 128 + c4 * 4];
        Xs[row * 132 + c4 * 4 + 0] = f2tf32(v.x);
        Xs[row * 132 + c4 * 4 + 1] = f2tf32(v.y);
        Xs[row * 132 + c4 * 4 + 2] = f2tf32(v.z);
        Xs[row * 132 + c4 * 4 + 3] = f2tf32(v.w);
    }

    for (int nb = 0; nb < 4; nb++) {
        float acc0[8][4] = {}, acc1[8][4] = {};
        gemm_ares2(Xs, Bs, w, 512, nb * 128, m0w, n0w, g, tg, t, acc0, acc1);

#pragma unroll
        for (int mi = 0; mi < 2; mi++) {
            float (*ac)[4] = mi ? acc1 : acc0;
            int r0 = m0w + mi * 16 + g;
#pragma unroll
            for (int s = 0; s < 8; s++) {
                int nl = n0w + s * 8 + 2 * tg;
                int ng = nb * 128 + nl;
                float b0v = b1[ng], b1v = b1[ng + 1];
                float h0 = ac[s][0] + b0v, h1 = ac[s][1] + b1v;
                float h2 = ac[s][2] + b0v, h3 = ac[s][3] + b1v;
                h0 = 0.5f * h0 * (1.f + erff(h0 * 0.70710678118654752f));
                h1 = 0.5f * h1 * (1.f + erff(h1 * 0.70710678118654752f));
                h2 = 0.5f * h2 * (1.f + erff(h2 * 0.70710678118654752f));
                h3 = 0.5f * h3 * (1.f + erff(h3 * 0.70710678118654752f));
                float* base = &g_h1[((size_t)tile * 128 + r0) * 512 + ng];
                *(float2*)base = make_float2(h0, h1);
                *(float2*)(base + 8 * 512) = make_float2(h2, h3);
            }
        }
    }
}

// ---------------- 5. FFN2 (K=512, A+B double-buffered) + LN2 + residual -> out ----------------
__global__ void __launch_bounds__(256) ffn2_mma(const float* __restrict__ w,
                                                const float* __restrict__ b2,
                                                const float* __restrict__ lg,
                                                const float* __restrict__ lb,
                                                float* __restrict__ out) {
    extern __shared__ __align__(16) unsigned char sm[];
    uint32_t* As = (uint32_t*)sm;               // 2 x [128][36]
    uint32_t* Bs = (uint32_t*)(sm + 36864);     // 2 x [32][136]
    float* Cs = (float*)sm;                     // epilogue reuse (67584 < 71680)

    int t = threadIdx.x;
    int tile = blockIdx.x;                      // 128 consecutive tokens

    const int lane = t & 31, g = lane >> 2, tg = lane & 3;
    const int warp = t >> 5;
    const int wm = warp & 3, wn = warp >> 2;
    const int m0w = wm * 32, n0w = wn * 64;

    const float* hp = g_h1 + (size_t)tile * 128 * 512;

    float4 pfB[4];
    float4 pfA[4];
    pf_b(pfB, w, 0, 128, 0, t);
#pragma unroll
    for (int it = 0; it < 4; it++) {
        int p = it * 256 + t;
        int row = p >> 3, k4 = p & 7;
        pfA[it] = *(const float4*)&hp[row * 512 + k4 * 4];
    }

    float acc0[8][4] = {}, acc1[8][4] = {};
    for (int k0 = 0; k0 < 16; k0++) {
        uint32_t* bufA = As + (k0 & 1) * 4608;
        uint32_t* bufB = Bs + (k0 & 1) * BCH;
        st_b(bufB, pfB, t);
#pragma unroll
        for (int it = 0; it < 4; it++) {
            int p = it * 256 + t;
            int row = p >> 3, k4 = p & 7;
            *(uint4*)&bufA[row * 36 + k4 * 4] =
                make_uint4(f2tf32(pfA[it].x), f2tf32(pfA[it].y), f2tf32(pfA[it].z), f2tf32(pfA[it].w));
        }
        __syncthreads();
        if (k0 < 15) {
            pf_b(pfB, w, (k0 + 1) * 32, 128, 0, t);
#pragma unroll
            for (int it = 0; it < 4; it++) {
                int p = it * 256 + t;
                int row = p >> 3, k4 = p & 7;
                pfA[it] = *(const float4*)&hp[row * 512 + (k0 + 1) * 32 + k4 * 4];
            }
        }
        mma_chunk2<36>(bufA, bufB, m0w, n0w, g, tg, 0, acc0, acc1);
    }

    __syncthreads();
#pragma unroll
    for (int mi = 0; mi < 2; mi++) {
        float (*ac)[4] = mi ? acc1 : acc0;
        int r0 = m0w + mi * 16 + g, r1 = r0 + 8;
#pragma unroll
        for (int s = 0; s < 8; s++) {
            int c = n0w + s * 8 + 2 * tg;
            float b0v = b2[c], b1v = b2[c + 1];
            Cs[r0 * 132 + c]     = ac[s][0] + b0v;
            Cs[r0 * 132 + c + 1] = ac[s][1] + b1v;
            Cs[r1 * 132 + c]     = ac[s][2] + b0v;
            Cs[r1 * 132 + c + 1] = ac[s][3] + b1v;
        }
    }
    __syncthreads();

    const float* sp = g_skip + (size_t)tile * 128 * 128;
    float4 lg4 = *(const float4*)&lg[lane * 4];
    float4 lb4 = *(const float4*)&lb[lane * 4];
    for (int i = 0; i < 16; i++) {
        int tk = warp * 16 + i;
        float4 v = *(const float4*)&Cs[tk * 132 + lane * 4];
        float s  = v.x + v.y + v.z + v.w;
        float ss = v.x * v.x + v.y * v.y + v.z * v.z + v.w * v.w;
#pragma unroll
        for (int o = 16; o; o >>= 1) {
            s  += __shfl_xor_sync(0xffffffffu, s, o);
            ss += __shfl_xor_sync(0xffffffffu, ss, o);
        }
        float mu = s * (1.f / 128.f);
        float var = ss * (1.f / 128.f) - mu * mu;
        float rs = rsqrtf(var + 1e-5f);
        float4 sk = *(const float4*)&sp[tk * 128 + lane * 4];
        float4 o4;
        o4.x = (v.x - mu) * rs * lg4.x + lb4.x + sk.x;
        o4.y = (v.y - mu) * rs * lg4.y + lb4.y + sk.y;
        o4.z = (v.z - mu) * rs * lg4.z + lb4.z + sk.z;
        o4.w = (v.w - mu) * rs * lg4.w + lb4.w + sk.w;
        *(float4*)&Cs[tk * 132 + lane * 4] = o4;
    }
    __syncthreads();

    // transposed write: 128 tokens = 2 image rows
    int b = tile >> 5;
    int y0 = (tile * 2) & 63;
    for (int it = 0; it < 64; it++) {
        int idx = it * 256 + t;
        int c = idx >> 7;
        int rest = idx & 127;
        int yloc = rest >> 6, xcol = rest & 63;
        out[((size_t)(b * 128 + c) * 64 + y0 + yloc) * 64 + xcol] = Cs[(yloc * 64 + xcol) * 132 + c];
    }
}

// ---------------- launch ----------------
extern "C" void kernel_launch(void* const* d_in, const int* in_sizes, int n_in,
                              void* d_out, int out_size) {
    (void)in_sizes; (void)n_in; (void)out_size;
    const float* x      = (const float*)d_in[0];
    const float* qkv_w  = (const float*)d_in[1];
    const float* qkv_b  = (const float*)d_in[2];
    const float* proj_w = (const float*)d_in[3];
    const float* proj_b = (const float*)d_in[4];
    const float* mw1    = (const float*)d_in[5];
    const float* mb1    = (const float*)d_in[6];
    const float* mw2    = (const float*)d_in[7];
    const float* mb2    = (const float*)d_in[8];
    const float* tau    = (const float*)d_in[9];
    const float* ln1_g  = (const float*)d_in[10];
    const float* ln1_b  = (const float*)d_in[11];
    const float* ln2_g  = (const float*)d_in[12];
    const float* ln2_b  = (const float*)d_in[13];
    const float* ffn_w1 = (const float*)d_in[14];
    const float* ffn_b1 = (const float*)d_in[15];
    const float* ffn_w2 = (const float*)d_in[16];
    const float* ffn_b2 = (const float*)d_in[17];
    float* out = (float*)d_out;

    cudaFuncSetAttribute(qkv_mma,  cudaFuncAttributeMaxDynamicSharedMemorySize, SMEM_ARES);
    cudaFuncSetAttribute(proj_mma, cudaFuncAttributeMaxDynamicSharedMemorySize, SMEM_ARES);
    cudaFuncSetAttribute(ffn1_mma, cudaFuncAttributeMaxDynamicSharedMemorySize, SMEM_ARES);
    cudaFuncSetAttribute(ffn2_mma, cudaFuncAttributeMaxDynamicSharedMemorySize, SMEM_FFN2);

    bias_kernel<<<64, 256>>>(mw1, mb1, mw2, mb2);
    qkv_mma<<<N_WIN / 2, 256, SMEM_ARES>>>(x, qkv_w, qkv_b);
    attn_mma<<<8192, 128>>>(tau);
    proj_mma<<<N_WIN / 2, 256, SMEM_ARES>>>(x, proj_w, proj_b, ln1_g, ln1_b);
    ffn1_mma<<<N_WIN / 2, 256, SMEM_ARES>>>(ffn_w1, ffn_b1);
    ffn2_mma<<<N_WIN / 2, 256, SMEM_FFN2>>>(ffn_w2, ffn_b2, ln2_g, ln2_b, out);
}

// round 9
// speedup vs baseline: 1.4159x; 1.0405x over previous
#include <cuda_runtime.h>
#include <math.h>
#include <stdint.h>

// B=32, C=128, H=W=64, WS=8, SHIFT=4, HEADS=4, TOK=64, NW=64, DH=32, HID=512
#define N_WIN   2048
#define N_TOK   131072

// ---------------- scratch ----------------
__device__ float    g_q[8192 * 2048];
__device__ float    g_k[8192 * 2048];
__device__ float    g_v[8192 * 2048];
__device__ uint32_t g_attn_t[N_WIN * 64 * 128];   // tf32 bits
__device__ float    g_skip[N_TOK * 128];
__device__ uint32_t g_h1t[N_TOK * 512];           // tf32 bits
__device__ float    g_bias[4 * 64 * 64];
// pre-converted tf32 weights
__device__ uint32_t g_wqkv[128 * 384];
__device__ uint32_t g_wproj[128 * 128];
__device__ uint32_t g_wf1[128 * 512];
__device__ uint32_t g_wf2[512 * 128];

// ---------------- helpers ----------------
__device__ __forceinline__ uint32_t f2tf32(float x) {
    uint32_t r;
    asm("cvt.rna.tf32.f32 %0, %1;" : "=r"(r) : "f"(x));
    return r;
}
__device__ __forceinline__ void mma8(float c[4], uint32_t a0, uint32_t a1, uint32_t a2, uint32_t a3,
                                     uint32_t b0, uint32_t b1) {
    asm volatile("mma.sync.aligned.m16n8k8.row.col.f32.tf32.tf32.f32 "
                 "{%0,%1,%2,%3},{%4,%5,%6,%7},{%8,%9},{%0,%1,%2,%3};"
                 : "+f"(c[0]), "+f"(c[1]), "+f"(c[2]), "+f"(c[3])
                 : "r"(a0), "r"(a1), "r"(a2), "r"(a3), "r"(b0), "r"(b1));
}
__device__ __forceinline__ uint32_t smem_u32(const void* p) {
    return (uint32_t)__cvta_generic_to_shared(p);
}
__device__ __forceinline__ void cpa16(uint32_t d, const void* s) {
    asm volatile("cp.async.cg.shared.global [%0], [%1], 16;" :: "r"(d), "l"(s) : "memory");
}
__device__ __forceinline__ void cpa8(uint32_t d, const void* s) {
    asm volatile("cp.async.ca.shared.global [%0], [%1], 8;" :: "r"(d), "l"(s) : "memory");
}
#define CP_COMMIT   asm volatile("cp.async.commit_group;" ::: "memory")
#define CP_WAIT(N)  asm volatile("cp.async.wait_group " #N ";" ::: "memory")

// 16-K chunk MMA; 128x128 block, warp tile 32x64. A at [row][ASTR], B chunk at [k][136].
template<int ASTR>
__device__ __forceinline__ void mma_k16(const uint32_t* __restrict__ As, const uint32_t* __restrict__ Bs,
                                        int m0w, int n0w, int g, int tg, int akbase,
                                        float acc0[8][4], float acc1[8][4]) {
#pragma unroll
    for (int ks = 0; ks < 2; ks++) {
        int kk = akbase + ks * 8;
        int bk = ks * 8;
        uint32_t a00 = As[(m0w + g) * ASTR + kk + tg];
        uint32_t a01 = As[(m0w + g + 8) * ASTR + kk + tg];
        uint32_t a02 = As[(m0w + g) * ASTR + kk + tg + 4];
        uint32_t a03 = As[(m0w + g + 8) * ASTR + kk + tg + 4];
        uint32_t a10 = As[(m0w + 16 + g) * ASTR + kk + tg];
        uint32_t a11 = As[(m0w + 24 + g) * ASTR + kk + tg];
        uint32_t a12 = As[(m0w + 16 + g) * ASTR + kk + tg + 4];
        uint32_t a13 = As[(m0w + 24 + g) * ASTR + kk + tg + 4];
#pragma unroll
        for (int s = 0; s < 8; s++) {
            uint32_t b0 = Bs[(bk + tg) * 136 + n0w + s * 8 + g];
            uint32_t b1 = Bs[(bk + tg + 4) * 136 + n0w + s * 8 + g];
            mma8(acc0[s], a00, a01, a02, a03, b0, b1);
            mma8(acc1[s], a10, a11, a12, a13, b0, b1);
        }
    }
}

// stage a 16k x 128n tf32 weight chunk into smem [16][136] via cp.async (8B ops)
__device__ __forceinline__ void stage_b16(uint32_t sbase, const uint32_t* __restrict__ Wt,
                                          int krow0, int WSTR, int nbase, int t) {
#pragma unroll
    for (int it = 0; it < 4; it++) {
        int u = it * 256 + t;                 // 1024 units: k(16) x n2(64)
        int k = u >> 6, n2 = u & 63;
        cpa8(sbase + (uint32_t)(k * 136 + n2 * 2) * 4,
             Wt + (size_t)(krow0 + k) * WSTR + nbase + n2 * 2);
    }
}

#define BCHB 8704      // bytes per B chunk (16*136*4)
#define BCHW 2176      // words per B chunk
#define SMEM_ARES 102400   // Xs 128*132*4 + 4*8704
#define SMEM_FFN2 75776    // 4*10240 (A) + 4*8704 (B)

// A-resident pipelined GEMM: 8 chunks of K=16, 4-buffer ring, stage distance 3.
__device__ __forceinline__ void gemm_pipe8(const uint32_t* __restrict__ Xs, const uint32_t* __restrict__ Bbuf,
                                           uint32_t bB, const uint32_t* __restrict__ Wt,
                                           int WSTR, int nbase,
                                           int m0w, int n0w, int g, int tg, int t,
                                           float acc0[8][4], float acc1[8][4]) {
    stage_b16(bB + 0 * BCHB, Wt,  0, WSTR, nbase, t); CP_COMMIT;
    stage_b16(bB + 1 * BCHB, Wt, 16, WSTR, nbase, t); CP_COMMIT;
    stage_b16(bB + 2 * BCHB, Wt, 32, WSTR, nbase, t); CP_COMMIT;
#pragma unroll 1
    for (int k0 = 0; k0 < 8; k0++) {
        if (k0 < 6)       { CP_WAIT(2); }
        else if (k0 == 6) { CP_WAIT(1); }
        else              { CP_WAIT(0); }
        __syncthreads();
        if (k0 + 3 < 8) { stage_b16(bB + ((k0 + 3) & 3) * BCHB, Wt, (k0 + 3) * 16, WSTR, nbase, t); CP_COMMIT; }
        mma_k16<132>(Xs, Bbuf + (k0 & 3) * BCHW, m0w, n0w, g, tg, k0 * 16, acc0, acc1);
    }
}

// ---------------- prep: weights fp32 -> tf32 ----------------
__global__ void prep_kernel(const float* __restrict__ qw, const float* __restrict__ pw,
                            const float* __restrict__ w1, const float* __restrict__ w2) {
    int i = blockIdx.x * 256 + threadIdx.x;      // 768 blocks -> 196608
    if (i < 49152)        g_wqkv[i]          = f2tf32(qw[i]);
    else if (i < 65536)   g_wproj[i - 49152] = f2tf32(pw[i - 49152]);
    else if (i < 131072)  g_wf1[i - 65536]   = f2tf32(w1[i - 65536]);
    else                  g_wf2[i - 131072]  = f2tf32(w2[i - 131072]);
}

// ---------------- bias (meta-MLP) ----------------
__global__ void __launch_bounds__(256) bias_kernel(const float* __restrict__ w1, const float* __restrict__ b1,
                                                   const float* __restrict__ w2, const float* __restrict__ b2) {
    __shared__ float sw1[512], sb1[256], sw2[1024], sb2[4];
    int t = threadIdx.x;
    sw1[t] = w1[t]; sw1[256 + t] = w1[256 + t];
    sb1[t] = b1[t];
#pragma unroll
    for (int i = 0; i < 4; i++) sw2[i * 256 + t] = w2[i * 256 + t];
    if (t < 4) sb2[t] = b2[t];
    __syncthreads();

    int o = blockIdx.x * 256 + t;
    int p = o >> 2, head = o & 3;
    int q = p >> 6, k = p & 63;
    float dy = (float)((q >> 3) - (k >> 3));
    float dx = (float)((q & 7) - (k & 7));
    float r0 = copysignf(log1pf(fabsf(dy)), dy);
    float r1 = copysignf(log1pf(fabsf(dx)), dx);
    float a = 0.f;
#pragma unroll 8
    for (int j = 0; j < 256; j++) {
        float h = fmaxf(r0 * sw1[j] + r1 * sw1[256 + j] + sb1[j], 0.f);
        a += h * sw2[j * 4 + head];
    }
    g_bias[head * 4096 + p] = a + sb2[head];
}

// ---------------- 1. QKV ----------------
__global__ void __launch_bounds__(256) qkv_mma(const float* __restrict__ x,
                                               const float* __restrict__ qb) {
    extern __shared__ __align__(16) unsigned char sm[];
    uint32_t* Xs = (uint32_t*)sm;                       // [128][132]
    uint32_t* Bbuf = (uint32_t*)(sm + 67584);
    uint32_t bB = smem_u32(sm + 67584);

    int t = threadIdx.x;
    int win0 = blockIdx.x * 2;
    int b = win0 >> 6;

    const int lane = t & 31, g = lane >> 2, tg = lane & 3;
    const int warp = t >> 5;
    const int wm = warp & 3, wn = warp >> 2;
    const int m0w = wm * 32, n0w = wn * 64;

    // gather 2 windows (roll -SHIFT) -> Xs tf32 [row][c]
#pragma unroll
    for (int it = 0; it < 16; it++) {
        int p = it * 256 + t;
        int wl = p >> 11;
        int q = p & 2047;
        int c = q >> 4;
        int r = (q >> 1) & 7;
        int half = q & 1;
        int win = win0 + wl;
        int wy = (win >> 3) & 7, wx = win & 7;
        int y  = (wy * 8 + r + 4) & 63;
        int xb = (wx * 8 + 4 + half * 4) & 63;
        float4 v = *(const float4*)&x[((size_t)(b * 128 + c) * 64 + y) * 64 + xb];
        int row = wl * 64 + r * 8 + half * 4;
        Xs[(row + 0) * 132 + c] = f2tf32(v.x);
        Xs[(row + 1) * 132 + c] = f2tf32(v.y);
        Xs[(row + 2) * 132 + c] = f2tf32(v.z);
        Xs[(row + 3) * 132 + c] = f2tf32(v.w);
    }

    for (int nb = 0; nb < 3; nb++) {
        float acc0[8][4] = {}, acc1[8][4] = {};
        gemm_pipe8(Xs, Bbuf, bB, g_wqkv, 384, nb * 128, m0w, n0w, g, tg, t, acc0, acc1);

        float* dst = (nb == 0) ? g_q : (nb == 1) ? g_k : g_v;
#pragma unroll
        for (int mi = 0; mi < 2; mi++) {
            float (*ac)[4] = mi ? acc1 : acc0;
            int r0 = m0w + mi * 16 + g;
            int win = win0 + (r0 >> 6);
            int tok = r0 & 63;
#pragma unroll
            for (int s = 0; s < 8; s++) {
                int nl = n0w + s * 8 + 2 * tg;
                int head = nl >> 5, d = nl & 31;
                float b0v = qb[nb * 128 + nl], b1v = qb[nb * 128 + nl + 1];
                float* base = &dst[((size_t)(win * 4 + head) * 64 + tok) * 32 + d];
                *(float2*)base = make_float2(ac[s][0] + b0v, ac[s][1] + b1v);
                *(float2*)(base + 8 * 32) = make_float2(ac[s][2] + b0v, ac[s][3] + b1v);
            }
        }
    }
}

// ---------------- 2. windowed attention (tf32 mma) -> g_attn_t ----------------
__global__ void __launch_bounds__(128) attn_mma(const float* __restrict__ tau) {
    __shared__ __align__(16) uint32_t Qs[64 * 36];
    __shared__ __align__(16) uint32_t Ks[64 * 36];
    __shared__ __align__(16) uint32_t Vs[64 * 36];
    __shared__ __align__(16) uint32_t Ps[64 * 68];
    __shared__ float qn[64], kn[64];
    __shared__ int   cnti[64];
    __shared__ float stau;

    int t = threadIdx.x;
    int wh = blockIdx.x;
    int win = wh >> 2, h = wh & 3;
    int wy = (win >> 3) & 7, wx = win & 7;

    const float* qp = g_q + (size_t)wh * 2048;
    const float* kp = g_k + (size_t)wh * 2048;
    const float* vp = g_v + (size_t)wh * 2048;

    for (int it = 0; it < 16; it++) {
        int idx = it * 128 + t;
        int tok = idx >> 5, d = idx & 31;
        Qs[tok * 36 + d] = f2tf32(qp[idx]);
        Ks[tok * 36 + d] = f2tf32(kp[idx]);
        Vs[tok * 36 + d] = f2tf32(vp[idx]);
    }
    if (t < 64) {
        int ys = wy * 8 + (t >> 3);
        int xs = wx * 8 + (t & 7);
        int ry = ys < 56 ? 0 : (ys < 60 ? 1 : 2);
        int rx = xs < 56 ? 0 : (xs < 60 ? 1 : 2);
        cnti[t] = ry * 3 + rx;
    }
    if (t == 0) stau = fmaxf(tau[h], 0.01f);
    {
        const float* rp = (t < 64) ? (qp + t * 32) : (kp + (t - 64) * 32);
        float s = 0.f;
#pragma unroll
        for (int d4 = 0; d4 < 8; d4++) {
            float4 v = *(const float4*)&rp[d4 * 4];
            s += v.x * v.x + v.y * v.y + v.z * v.z + v.w * v.w;
        }
        float nv = sqrtf(s);
        if (t < 64) qn[t] = nv; else kn[t - 64] = nv;
    }
    __syncthreads();

    const int lane = t & 31, g = lane >> 2, tg = lane & 3;
    const int wid = t >> 5;
    const int m0 = wid * 16;
    const int r0 = m0 + g, r1 = r0 + 8;

    float acc[8][4] = {};
#pragma unroll
    for (int ks = 0; ks < 4; ks++) {
        int kk = ks * 8;
        uint32_t a0 = Qs[r0 * 36 + kk + tg];
        uint32_t a1 = Qs[r1 * 36 + kk + tg];
        uint32_t a2 = Qs[r0 * 36 + kk + tg + 4];
        uint32_t a3 = Qs[r1 * 36 + kk + tg + 4];
#pragma unroll
        for (int s = 0; s < 8; s++) {
            uint32_t b0 = Ks[(s * 8 + g) * 36 + kk + tg];
            uint32_t b1 = Ks[(s * 8 + g) * 36 + kk + tg + 4];
            mma8(acc[s], a0, a1, a2, a3, b0, b1);
        }
    }

    float tv = stau;
    float qn0 = qn[r0], qn1 = qn[r1];
    int mq0 = cnti[r0], mq1 = cnti[r1];
    const float* bias0 = &g_bias[h * 4096 + r0 * 64];
    const float* bias1 = &g_bias[h * 4096 + r1 * 64];
#pragma unroll
    for (int s = 0; s < 8; s++) {
        int c0 = s * 8 + 2 * tg;
        float kn0 = kn[c0], kn1 = kn[c0 + 1];
        float2 bA = *(const float2*)&bias0[c0];
        float2 bB = *(const float2*)&bias1[c0];
        int mk0 = cnti[c0], mk1 = cnti[c0 + 1];
        acc[s][0] = acc[s][0] / fmaxf(qn0 * kn0, 1e-6f) / tv + bA.x + (mq0 != mk0 ? -100.f : 0.f);
        acc[s][1] = acc[s][1] / fmaxf(qn0 * kn1, 1e-6f) / tv + bA.y + (mq0 != mk1 ? -100.f : 0.f);
        acc[s][2] = acc[s][2] / fmaxf(qn1 * kn0, 1e-6f) / tv + bB.x + (mq1 != mk0 ? -100.f : 0.f);
        acc[s][3] = acc[s][3] / fmaxf(qn1 * kn1, 1e-6f) / tv + bB.y + (mq1 != mk1 ? -100.f : 0.f);
    }

    float mx0 = -1e30f, mx1 = -1e30f;
#pragma unroll
    for (int s = 0; s < 8; s++) {
        mx0 = fmaxf(mx0, fmaxf(acc[s][0], acc[s][1]));
        mx1 = fmaxf(mx1, fmaxf(acc[s][2], acc[s][3]));
    }
#pragma unroll
    for (int o = 1; o <= 2; o <<= 1) {
        mx0 = fmaxf(mx0, __shfl_xor_sync(0xffffffffu, mx0, o));
        mx1 = fmaxf(mx1, __shfl_xor_sync(0xffffffffu, mx1, o));
    }
    float sm0 = 0.f, sm1 = 0.f;
#pragma unroll
    for (int s = 0; s < 8; s++) {
        acc[s][0] = expf(acc[s][0] - mx0);
        acc[s][1] = expf(acc[s][1] - mx0);
        acc[s][2] = expf(acc[s][2] - mx1);
        acc[s][3] = expf(acc[s][3] - mx1);
        sm0 += acc[s][0] + acc[s][1];
        sm1 += acc[s][2] + acc[s][3];
    }
#pragma unroll
    for (int o = 1; o <= 2; o <<= 1) {
        sm0 += __shfl_xor_sync(0xffffffffu, sm0, o);
        sm1 += __shfl_xor_sync(0xffffffffu, sm1, o);
    }
    float inv0 = 1.f / sm0, inv1 = 1.f / sm1;
#pragma unroll
    for (int s = 0; s < 8; s++) {
        int c0 = s * 8 + 2 * tg;
        Ps[r0 * 68 + c0]     = f2tf32(acc[s][0] * inv0);
        Ps[r0 * 68 + c0 + 1] = f2tf32(acc[s][1] * inv0);
        Ps[r1 * 68 + c0]     = f2tf32(acc[s][2] * inv1);
        Ps[r1 * 68 + c0 + 1] = f2tf32(acc[s][3] * inv1);
    }
    __syncwarp();

    float oacc[4][4] = {};
#pragma unroll
    for (int ks = 0; ks < 8; ks++) {
        int kk = ks * 8;
        uint32_t a0 = Ps[r0 * 68 + kk + tg];
        uint32_t a1 = Ps[r1 * 68 + kk + tg];
        uint32_t a2 = Ps[r0 * 68 + kk + tg + 4];
        uint32_t a3 = Ps[r1 * 68 + kk + tg + 4];
#pragma unroll
        for (int s2 = 0; s2 < 4; s2++) {
            uint32_t b0 = Vs[(kk + tg) * 36 + s2 * 8 + g];
            uint32_t b1 = Vs[(kk + tg + 4) * 36 + s2 * 8 + g];
            mma8(oacc[s2], a0, a1, a2, a3, b0, b1);
        }
    }

#pragma unroll
    for (int s2 = 0; s2 < 4; s2++) {
        int dc = s2 * 8 + 2 * tg;
        *(uint2*)&g_attn_t[((size_t)win * 64 + r0) * 128 + h * 32 + dc] =
            make_uint2(f2tf32(oacc[s2][0]), f2tf32(oacc[s2][1]));
        *(uint2*)&g_attn_t[((size_t)win * 64 + r1) * 128 + h * 32 + dc] =
            make_uint2(f2tf32(oacc[s2][2]), f2tf32(oacc[s2][3]));
    }
}

// ---------------- 3. proj + LN1 + residual -> g_skip ----------------
__global__ void __launch_bounds__(256) proj_mma(const float* __restrict__ x,
                                                const float* __restrict__ pb,
                                                const float* __restrict__ lg,
                                                const float* __restrict__ lb) {
    extern __shared__ __align__(16) unsigned char sm[];
    uint32_t* Xs = (uint32_t*)sm;
    uint32_t* Bbuf = (uint32_t*)(sm + 67584);
    uint32_t bB = smem_u32(sm + 67584);
    uint32_t bX = smem_u32(sm);
    float* Cs = (float*)sm;

    int t = threadIdx.x;
    int win0 = blockIdx.x * 2;
    int b = win0 >> 6;

    const int lane = t & 31, g = lane >> 2, tg = lane & 3;
    const int warp = t >> 5;
    const int wm = warp & 3, wn = warp >> 2;
    const int m0w = wm * 32, n0w = wn * 64;

    // async A load (tf32 already)
    const uint32_t* ap = g_attn_t + (size_t)win0 * 64 * 128;
#pragma unroll
    for (int it = 0; it < 16; it++) {
        int u = it * 256 + t;                 // 4096 16B units: row(128) x c4(32)
        int row = u >> 5, c4 = u & 31;
        cpa16(bX + (uint32_t)(row * 132 + c4 * 4) * 4, ap + row * 128 + c4 * 4);
    }
    CP_COMMIT;

    float acc0[8][4] = {}, acc1[8][4] = {};
    gemm_pipe8(Xs, Bbuf, bB, g_wproj, 128, 0, m0w, n0w, g, tg, t, acc0, acc1);

    __syncthreads();
#pragma unroll
    for (int mi = 0; mi < 2; mi++) {
        float (*ac)[4] = mi ? acc1 : acc0;
        int r0 = m0w + mi * 16 + g, r1 = r0 + 8;
#pragma unroll
        for (int s = 0; s < 8; s++) {
            int c = n0w + s * 8 + 2 * tg;
            float b0v = pb[c], b1v = pb[c + 1];
            Cs[r0 * 132 + c]     = ac[s][0] + b0v;
            Cs[r0 * 132 + c + 1] = ac[s][1] + b1v;
            Cs[r1 * 132 + c]     = ac[s][2] + b0v;
            Cs[r1 * 132 + c + 1] = ac[s][3] + b1v;
        }
    }
    __syncthreads();

    float4 lg4 = *(const float4*)&lg[lane * 4];
    float4 lb4 = *(const float4*)&lb[lane * 4];
    for (int i = 0; i < 16; i++) {
        int tk = warp * 16 + i;
        float4 v = *(const float4*)&Cs[tk * 132 + lane * 4];
        float s  = v.x + v.y + v.z + v.w;
        float ss = v.x * v.x + v.y * v.y + v.z * v.z + v.w * v.w;
#pragma unroll
        for (int o = 16; o; o >>= 1) {
            s  += __shfl_xor_sync(0xffffffffu, s, o);
            ss += __shfl_xor_sync(0xffffffffu, ss, o);
        }
        float mu = s * (1.f / 128.f);
        float var = ss * (1.f / 128.f) - mu * mu;
        float rs = rsqrtf(var + 1e-5f);

        int win = win0 + (tk >> 6);
        int wy = (win >> 3) & 7, wx = win & 7;
        int tokl = tk & 63;
        int y  = (wy * 8 + (tokl >> 3) + 4) & 63;
        int xx = (wx * 8 + (tokl & 7) + 4) & 63;
        const float* xr = x + ((size_t)(b * 128 + lane * 4) * 64 + y) * 64 + xx;
        float4 o4;
        o4.x = (v.x - mu) * rs * lg4.x + lb4.x + xr[0];
        o4.y = (v.y - mu) * rs * lg4.y + lb4.y + xr[4096];
        o4.z = (v.z - mu) * rs * lg4.z + lb4.z + xr[8192];
        o4.w = (v.w - mu) * rs * lg4.w + lb4.w + xr[12288];
        *(float4*)&g_skip[((size_t)b * 4096 + y * 64 + xx) * 128 + lane * 4] = o4;
    }
}

// ---------------- 4. FFN1 + GELU -> g_h1t ----------------
__global__ void __launch_bounds__(256) ffn1_mma(const float* __restrict__ b1) {
    extern __shared__ __align__(16) unsigned char sm[];
    uint32_t* Xs = (uint32_t*)sm;
    uint32_t* Bbuf = (uint32_t*)(sm + 67584);
    uint32_t bB = smem_u32(sm + 67584);

    int t = threadIdx.x;
    int tile = blockIdx.x;

    const int lane = t & 31, g = lane >> 2, tg = lane & 3;
    const int warp = t >> 5;
    const int wm = warp & 3, wn = warp >> 2;
    const int m0w = wm * 32, n0w = wn * 64;

    const float* sp = g_skip + (size_t)tile * 128 * 128;
#pragma unroll
    for (int it = 0; it < 16; it++) {
        int p = it * 256 + t;
        int row = p >> 5, c4 = p & 31;
        float4 v = *(const float4*)&sp[row * 128 + c4 * 4];
        Xs[row * 132 + c4 * 4 + 0] = f2tf32(v.x);
        Xs[row * 132 + c4 * 4 + 1] = f2tf32(v.y);
        Xs[row * 132 + c4 * 4 + 2] = f2tf32(v.z);
        Xs[row * 132 + c4 * 4 + 3] = f2tf32(v.w);
    }

    for (int nb = 0; nb < 4; nb++) {
        float acc0[8][4] = {}, acc1[8][4] = {};
        gemm_pipe8(Xs, Bbuf, bB, g_wf1, 512, nb * 128, m0w, n0w, g, tg, t, acc0, acc1);

#pragma unroll
        for (int mi = 0; mi < 2; mi++) {
            float (*ac)[4] = mi ? acc1 : acc0;
            int r0 = m0w + mi * 16 + g;
#pragma unroll
            for (int s = 0; s < 8; s++) {
                int nl = n0w + s * 8 + 2 * tg;
                int ng = nb * 128 + nl;
                float b0v = b1[ng], b1v = b1[ng + 1];
                float h0 = ac[s][0] + b0v, h1 = ac[s][1] + b1v;
                float h2 = ac[s][2] + b0v, h3 = ac[s][3] + b1v;
                h0 = 0.5f * h0 * (1.f + erff(h0 * 0.70710678118654752f));
                h1 = 0.5f * h1 * (1.f + erff(h1 * 0.70710678118654752f));
                h2 = 0.5f * h2 * (1.f + erff(h2 * 0.70710678118654752f));
                h3 = 0.5f * h3 * (1.f + erff(h3 * 0.70710678118654752f));
                uint32_t* base = &g_h1t[((size_t)tile * 128 + r0) * 512 + ng];
                *(uint2*)base = make_uint2(f2tf32(h0), f2tf32(h1));
                *(uint2*)(base + 8 * 512) = make_uint2(f2tf32(h2), f2tf32(h3));
            }
        }
    }
}

// ---------------- 5. FFN2 (K=512, dual async streams) + LN2 + residual -> out ----------------
__global__ void __launch_bounds__(256) ffn2_mma(const float* __restrict__ b2,
                                                const float* __restrict__ lg,
                                                const float* __restrict__ lb,
                                                float* __restrict__ out) {
    extern __shared__ __align__(16) unsigned char sm[];
    uint32_t* Abuf = (uint32_t*)sm;               // 4 x [128][20]
    uint32_t* Bbuf = (uint32_t*)(sm + 40960);     // 4 x [16][136]
    uint32_t bA = smem_u32(sm);
    uint32_t bB = smem_u32(sm + 40960);
    float* Cs = (float*)sm;

    int t = threadIdx.x;
    int tile = blockIdx.x;

    const int lane = t & 31, g = lane >> 2, tg = lane & 3;
    const int warp = t >> 5;
    const int wm = warp & 3, wn = warp >> 2;
    const int m0w = wm * 32, n0w = wn * 64;

    const uint32_t* hp = g_h1t + (size_t)tile * 128 * 512;

    // stage chunk c: A 128x16 from hp, B 16x128 from g_wf2
    auto stage_a = [&](uint32_t sbase, int kcol0) {
#pragma unroll
        for (int it = 0; it < 4; it++) {
            int u = it * 256 + t;             // 1024 8B units: row(128) x q(8)
            int row = u >> 3, q = u & 7;
            cpa8(sbase + (uint32_t)(row * 20 + q * 2) * 4, hp + (size_t)row * 512 + kcol0 + q * 2);
        }
    };

    stage_a(bA + 0 * 10240, 0);  stage_b16(bB + 0 * BCHB, g_wf2,  0, 128, 0, t); CP_COMMIT;
    stage_a(bA + 1 * 10240, 16); stage_b16(bB + 1 * BCHB, g_wf2, 16, 128, 0, t); CP_COMMIT;
    stage_a(bA + 2 * 10240, 32); stage_b16(bB + 2 * BCHB, g_wf2, 32, 128, 0, t); CP_COMMIT;

    float acc0[8][4] = {}, acc1[8][4] = {};
#pragma unroll 1
    for (int c = 0; c < 32; c++) {
        if (c < 30)       { CP_WAIT(2); }
        else if (c == 30) { CP_WAIT(1); }
        else              { CP_WAIT(0); }
        __syncthreads();
        if (c + 3 < 32) {
            stage_a(bA + ((c + 3) & 3) * 10240, (c + 3) * 16);
            stage_b16(bB + ((c + 3) & 3) * BCHB, g_wf2, (c + 3) * 16, 128, 0, t);
            CP_COMMIT;
        }
        mma_k16<20>(Abuf + (c & 3) * 2560, Bbuf + (c & 3) * BCHW, m0w, n0w, g, tg, 0, acc0, acc1);
    }

    __syncthreads();
#pragma unroll
    for (int mi = 0; mi < 2; mi++) {
        float (*ac)[4] = mi ? acc1 : acc0;
        int r0 = m0w + mi * 16 + g, r1 = r0 + 8;
#pragma unroll
        for (int s = 0; s < 8; s++) {
            int c = n0w + s * 8 + 2 * tg;
            float b0v = b2[c], b1v = b2[c + 1];
            Cs[r0 * 132 + c]     = ac[s][0] + b0v;
            Cs[r0 * 132 + c + 1] = ac[s][1] + b1v;
            Cs[r1 * 132 + c]     = ac[s][2] + b0v;
            Cs[r1 * 132 + c + 1] = ac[s][3] + b1v;
        }
    }
    __syncthreads();

    const float* sp = g_skip + (size_t)tile * 128 * 128;
    float4 lg4 = *(const float4*)&lg[lane * 4];
    float4 lb4 = *(const float4*)&lb[lane * 4];
    for (int i = 0; i < 16; i++) {
        int tk = warp * 16 + i;
        float4 v = *(const float4*)&Cs[tk * 132 + lane * 4];
        float s  = v.x + v.y + v.z + v.w;
        float ss = v.x * v.x + v.y * v.y + v.z * v.z + v.w * v.w;
#pragma unroll
        for (int o = 16; o; o >>= 1) {
            s  += __shfl_xor_sync(0xffffffffu, s, o);
            ss += __shfl_xor_sync(0xffffffffu, ss, o);
        }
        float mu = s * (1.f / 128.f);
        float var = ss * (1.f / 128.f) - mu * mu;
        float rs = rsqrtf(var + 1e-5f);
        float4 sk = *(const float4*)&sp[tk * 128 + lane * 4];
        float4 o4;
        o4.x = (v.x - mu) * rs * lg4.x + lb4.x + sk.x;
        o4.y = (v.y - mu) * rs * lg4.y + lb4.y + sk.y;
        o4.z = (v.z - mu) * rs * lg4.z + lb4.z + sk.z;
        o4.w = (v.w - mu) * rs * lg4.w + lb4.w + sk.w;
        *(float4*)&Cs[tk * 132 + lane * 4] = o4;
    }
    __syncthreads();

    int b = tile >> 5;
    int y0 = (tile * 2) & 63;
    for (int it = 0; it < 64; it++) {
        int idx = it * 256 + t;
        int c = idx >> 7;
        int rest = idx & 127;
        int yloc = rest >> 6, xcol = rest & 63;
        out[((size_t)(b * 128 + c) * 64 + y0 + yloc) * 64 + xcol] = Cs[(yloc * 64 + xcol) * 132 + c];
    }
}

// ---------------- launch ----------------
extern "C" void kernel_launch(void* const* d_in, const int* in_sizes, int n_in,
                              void* d_out, int out_size) {
    (void)in_sizes; (void)n_in; (void)out_size;
    const float* x      = (const float*)d_in[0];
    const float* qkv_w  = (const float*)d_in[1];
    const float* qkv_b  = (const float*)d_in[2];
    const float* proj_w = (const float*)d_in[3];
    const float* proj_b = (const float*)d_in[4];
    const float* mw1    = (const float*)d_in[5];
    const float* mb1    = (const float*)d_in[6];
    const float* mw2    = (const float*)d_in[7];
    const float* mb2    = (const float*)d_in[8];
    const float* tau    = (const float*)d_in[9];
    const float* ln1_g  = (const float*)d_in[10];
    const float* ln1_b  = (const float*)d_in[11];
    const float* ln2_g  = (const float*)d_in[12];
    const float* ln2_b  = (const float*)d_in[13];
    const float* ffn_w1 = (const float*)d_in[14];
    const float* ffn_b1 = (const float*)d_in[15];
    const float* ffn_w2 = (const float*)d_in[16];
    const float* ffn_b2 = (const float*)d_in[17];
    float* out = (float*)d_out;

    cudaFuncSetAttribute(qkv_mma,  cudaFuncAttributeMaxDynamicSharedMemorySize, SMEM_ARES);
    cudaFuncSetAttribute(proj_mma, cudaFuncAttributeMaxDynamicSharedMemorySize, SMEM_ARES);
    cudaFuncSetAttribute(ffn1_mma, cudaFuncAttributeMaxDynamicSharedMemorySize, SMEM_ARES);
    cudaFuncSetAttribute(ffn2_mma, cudaFuncAttributeMaxDynamicSharedMemorySize, SMEM_FFN2);

    prep_kernel<<<768, 256>>>(qkv_w, proj_w, ffn_w1, ffn_w2);
    bias_kernel<<<64, 256>>>(mw1, mb1, mw2, mb2);
    qkv_mma<<<N_WIN / 2, 256, SMEM_ARES>>>(x, qkv_b);
    attn_mma<<<8192, 128>>>(tau);
    proj_mma<<<N_WIN / 2, 256, SMEM_ARES>>>(x, proj_b, ln1_g, ln1_b);
    ffn1_mma<<<N_WIN / 2, 256, SMEM_ARES>>>(ffn_b1);
    ffn2_mma<<<N_WIN / 2, 256, SMEM_FFN2>>>(ffn_b2, ln2_g, ln2_b, out);
}